// round 1
// baseline (speedup 1.0000x reference)
#include <cuda_runtime.h>

// TriangleMultiplicativeUpdate (outgoing), B=1, N=512, C=128, fp32.
// Pipeline: kP (LN + 5 projections + gates) -> kE (per-channel einsum GEMMs) -> kF (LN + w_z + gating)

#define NPOS   262144      // 512*512 positions
#define NSEQ   512
#define CDIM   128

// Scratch (channel-group-major float4: [cg][i][k], cg = c/4, 32 groups)
__device__ float4 d_A4[8388608];   // 134 MB
__device__ float4 d_B4[8388608];   // 134 MB
__device__ float4 d_X4[8388608];   // 134 MB  ([cg][i][j])
__device__ float  d_G [33554432];  // 134 MB  natural [pos][c]

__device__ __forceinline__ float sigf(float x) { return 1.0f / (1.0f + __expf(-x)); }

// LayerNorm of 64 rows x 128 cols held in shared memory (row stride 132).
// 8 warps, each warp owns 8 rows; 4 elements per lane.
__device__ __forceinline__ void ln_rows(float (*s)[132],
                                        const float* __restrict__ g,
                                        const float* __restrict__ b) {
    const int warp = threadIdx.x >> 5, lane = threadIdx.x & 31;
    const float g0 = g[lane], g1 = g[lane+32], g2 = g[lane+64], g3 = g[lane+96];
    const float b0 = b[lane], b1 = b[lane+32], b2 = b[lane+64], b3 = b[lane+96];
    #pragma unroll 1
    for (int rr = 0; rr < 8; rr++) {
        const int r = warp * 8 + rr;
        float v0 = s[r][lane], v1 = s[r][lane+32], v2 = s[r][lane+64], v3 = s[r][lane+96];
        float sm = (v0 + v1) + (v2 + v3);
        float sq = fmaf(v0, v0, fmaf(v1, v1, fmaf(v2, v2, v3 * v3)));
        #pragma unroll
        for (int o = 16; o > 0; o >>= 1) {
            sm += __shfl_xor_sync(0xffffffffu, sm, o);
            sq += __shfl_xor_sync(0xffffffffu, sq, o);
        }
        const float mean = sm * 0.0078125f;                    // /128
        const float var  = fmaf(-mean, mean, sq * 0.0078125f); // E[x^2]-m^2
        const float rs   = rsqrtf(var + 1e-5f);
        s[r][lane]    = fmaf((v0 - mean) * rs, g0, b0);
        s[r][lane+32] = fmaf((v1 - mean) * rs, g1, b1);
        s[r][lane+64] = fmaf((v2 - mean) * rs, g2, b2);
        s[r][lane+96] = fmaf((v3 - mean) * rs, g3, b3);
    }
}

// GEMM pass: zn[64x128] @ [Wgate | Wproj] (128 x 256).  Thread micro-tile:
// 8 positions (rows r = ty + 8*pi) x 4 channels (c = tx*4..tx*4+3) for each of gate/proj.
__device__ __forceinline__ void gemm_pass_pair(
    const float (*s_zn)[132], float (*s_w)[256],
    const float* __restrict__ wg, const float* __restrict__ wp,
    float accg[8][4], float accp[8][4])
{
    const int t = threadIdx.x;
    const int tx = t & 31, ty = t >> 5;
    #pragma unroll 1
    for (int k0 = 0; k0 < 128; k0 += 8) {
        __syncthreads();
        #pragma unroll
        for (int l = 0; l < 8; l++) {
            // rk = l, c = t (256 threads cover one 256-wide row per l)
            s_w[l][t] = (t < 128) ? wg[(k0 + l) * 128 + t]
                                  : wp[(k0 + l) * 128 + (t - 128)];
        }
        __syncthreads();
        #pragma unroll
        for (int kk = 0; kk < 8; kk++) {
            const float4 bgv = *(const float4*)&s_w[kk][tx * 4];
            const float4 bpv = *(const float4*)&s_w[kk][128 + tx * 4];
            #pragma unroll
            for (int pi = 0; pi < 8; pi++) {
                const float av = s_zn[ty + 8 * pi][k0 + kk];   // warp-broadcast
                accg[pi][0] = fmaf(av, bgv.x, accg[pi][0]);
                accg[pi][1] = fmaf(av, bgv.y, accg[pi][1]);
                accg[pi][2] = fmaf(av, bgv.z, accg[pi][2]);
                accg[pi][3] = fmaf(av, bgv.w, accg[pi][3]);
                accp[pi][0] = fmaf(av, bpv.x, accp[pi][0]);
                accp[pi][1] = fmaf(av, bpv.y, accp[pi][1]);
                accp[pi][2] = fmaf(av, bpv.z, accp[pi][2]);
                accp[pi][3] = fmaf(av, bpv.w, accp[pi][3]);
            }
        }
    }
}

__device__ __forceinline__ void gemm_pass_single(
    const float (*s_zn)[132], float (*s_w)[256],
    const float* __restrict__ w, float acc[8][4])
{
    const int t = threadIdx.x;
    const int tx = t & 31, ty = t >> 5;
    #pragma unroll 1
    for (int k0 = 0; k0 < 128; k0 += 8) {
        __syncthreads();
        #pragma unroll
        for (int l = 0; l < 4; l++) {
            const int idx = t + l * 256;
            const int rk = idx >> 7, c = idx & 127;
            s_w[rk][c] = w[(k0 + rk) * 128 + c];
        }
        __syncthreads();
        #pragma unroll
        for (int kk = 0; kk < 8; kk++) {
            const float4 wv = *(const float4*)&s_w[kk][tx * 4];
            #pragma unroll
            for (int pi = 0; pi < 8; pi++) {
                const float av = s_zn[ty + 8 * pi][k0 + kk];
                acc[pi][0] = fmaf(av, wv.x, acc[pi][0]);
                acc[pi][1] = fmaf(av, wv.y, acc[pi][1]);
                acc[pi][2] = fmaf(av, wv.z, acc[pi][2]);
                acc[pi][3] = fmaf(av, wv.w, acc[pi][3]);
            }
        }
    }
}

__device__ __forceinline__ void epilogue_pair(
    const float accg[8][4], const float accp[8][4],
    const float* __restrict__ bgp, const float* __restrict__ bpp,
    const float* __restrict__ mask, int pos0, int i_idx, int k_base,
    float4* __restrict__ dst)
{
    const int t = threadIdx.x;
    const int tx = t & 31, ty = t >> 5;
    const float4 bg = *(const float4*)&bgp[tx * 4];
    const float4 bp = *(const float4*)&bpp[tx * 4];
    #pragma unroll
    for (int pi = 0; pi < 8; pi++) {
        const int r = ty + 8 * pi;
        const float mk = mask[pos0 + r];
        float4 o;
        o.x = mk * sigf(accg[pi][0] + bg.x) * (accp[pi][0] + bp.x);
        o.y = mk * sigf(accg[pi][1] + bg.y) * (accp[pi][1] + bp.y);
        o.z = mk * sigf(accg[pi][2] + bg.z) * (accp[pi][2] + bp.z);
        o.w = mk * sigf(accg[pi][3] + bg.w) * (accp[pi][3] + bp.w);
        dst[(size_t)tx * 262144 + (size_t)i_idx * 512 + (k_base + r)] = o;
    }
}

// ---------------- kP: LN + projections -------------------------------------
__global__ __launch_bounds__(256) void kP(
    const float* __restrict__ z,    const float* __restrict__ mask,
    const float* __restrict__ w_ag, const float* __restrict__ b_ag,
    const float* __restrict__ w_ap, const float* __restrict__ b_ap,
    const float* __restrict__ w_bg, const float* __restrict__ b_bg,
    const float* __restrict__ w_bp, const float* __restrict__ b_bp,
    const float* __restrict__ w_g,  const float* __restrict__ b_g,
    const float* __restrict__ lng,  const float* __restrict__ lnb)
{
    __shared__ float s_zn[64][132];
    __shared__ float s_w[8][256];
    const int t = threadIdx.x;
    const int pos0 = blockIdx.x * 64;       // 64 consecutive positions, same i
    const int i_idx = pos0 >> 9;
    const int k_base = pos0 & 511;

    // load z tile (coalesced) and LayerNorm it in shared
    #pragma unroll
    for (int l = 0; l < 32; l++) {
        const int idx = t + l * 256;        // 0..8191
        s_zn[idx >> 7][idx & 127] = z[(size_t)pos0 * 128 + idx];
    }
    __syncthreads();
    ln_rows(s_zn, lng, lnb);
    __syncthreads();

    float accg[8][4], accp[8][4];

    // pass 1: a = mask * sigmoid(zn@w_ag+b_ag) * (zn@w_ap+b_ap)
    #pragma unroll
    for (int pi = 0; pi < 8; pi++)
        #pragma unroll
        for (int ci = 0; ci < 4; ci++) { accg[pi][ci] = 0.f; accp[pi][ci] = 0.f; }
    gemm_pass_pair(s_zn, s_w, w_ag, w_ap, accg, accp);
    epilogue_pair(accg, accp, b_ag, b_ap, mask, pos0, i_idx, k_base, d_A4);

    // pass 2: b
    #pragma unroll
    for (int pi = 0; pi < 8; pi++)
        #pragma unroll
        for (int ci = 0; ci < 4; ci++) { accg[pi][ci] = 0.f; accp[pi][ci] = 0.f; }
    gemm_pass_pair(s_zn, s_w, w_bg, w_bp, accg, accp);
    epilogue_pair(accg, accp, b_bg, b_bp, mask, pos0, i_idx, k_base, d_B4);

    // pass 3: g = sigmoid(zn@w_g + b_g)  (natural layout, no mask)
    #pragma unroll
    for (int pi = 0; pi < 8; pi++)
        #pragma unroll
        for (int ci = 0; ci < 4; ci++) accg[pi][ci] = 0.f;
    gemm_pass_single(s_zn, s_w, w_g, accg);
    {
        const int tx = t & 31, ty = t >> 5;
        const float4 bgv = *(const float4*)&b_g[tx * 4];
        #pragma unroll
        for (int pi = 0; pi < 8; pi++) {
            const int r = ty + 8 * pi;
            float4 o;
            o.x = sigf(accg[pi][0] + bgv.x);
            o.y = sigf(accg[pi][1] + bgv.y);
            o.z = sigf(accg[pi][2] + bgv.z);
            o.w = sigf(accg[pi][3] + bgv.w);
            *(float4*)&d_G[(size_t)(pos0 + r) * 128 + tx * 4] = o;
        }
    }
}

// ---------------- kE: einsum bikc,bjkc->bijc --------------------------------
// One block per (i-tile 64, j-tile 64, channel-group of 4). K = 512 in steps of 16.
__global__ __launch_bounds__(256) void kE()
{
    __shared__ float4 s_a[64][17];
    __shared__ float4 s_b[64][17];
    const int t = threadIdx.x;
    const int tx = t & 15, ty = t >> 4;                 // 16x16 thread grid
    const int j0 = blockIdx.x * 64, i0 = blockIdx.y * 64;
    const size_t cgo = (size_t)blockIdx.z * (512 * 512);
    const float4* __restrict__ Ab = d_A4 + cgo + (size_t)i0 * 512;
    const float4* __restrict__ Bb = d_B4 + cgo + (size_t)j0 * 512;

    float4 acc[4][4];
    #pragma unroll
    for (int a = 0; a < 4; a++)
        #pragma unroll
        for (int b = 0; b < 4; b++) acc[a][b] = make_float4(0.f, 0.f, 0.f, 0.f);

    const int lr = t >> 4, lk = t & 15;
    #pragma unroll 1
    for (int kt = 0; kt < 32; kt++) {
        __syncthreads();
        #pragma unroll
        for (int rep = 0; rep < 4; rep++) {
            const int r = lr + rep * 16;
            s_a[r][lk] = Ab[(size_t)r * 512 + kt * 16 + lk];
            s_b[r][lk] = Bb[(size_t)r * 512 + kt * 16 + lk];
        }
        __syncthreads();
        #pragma unroll 4
        for (int kk = 0; kk < 16; kk++) {
            float4 af[4], bf[4];
            #pragma unroll
            for (int ii = 0; ii < 4; ii++) af[ii] = s_a[ty + 16 * ii][kk];
            #pragma unroll
            for (int jj = 0; jj < 4; jj++) bf[jj] = s_b[tx + 16 * jj][kk];
            #pragma unroll
            for (int ii = 0; ii < 4; ii++)
                #pragma unroll
                for (int jj = 0; jj < 4; jj++) {
                    acc[ii][jj].x = fmaf(af[ii].x, bf[jj].x, acc[ii][jj].x);
                    acc[ii][jj].y = fmaf(af[ii].y, bf[jj].y, acc[ii][jj].y);
                    acc[ii][jj].z = fmaf(af[ii].z, bf[jj].z, acc[ii][jj].z);
                    acc[ii][jj].w = fmaf(af[ii].w, bf[jj].w, acc[ii][jj].w);
                }
        }
    }
    float4* __restrict__ Xb = d_X4 + cgo;
    #pragma unroll
    for (int ii = 0; ii < 4; ii++) {
        const int i = i0 + ty + 16 * ii;
        #pragma unroll
        for (int jj = 0; jj < 4; jj++)
            Xb[(size_t)i * 512 + (j0 + tx + 16 * jj)] = acc[ii][jj];
    }
}

// ---------------- kF: LN(x) @ w_z + b_z, * g --------------------------------
__global__ __launch_bounds__(256) void kF(
    const float* __restrict__ lng, const float* __restrict__ lnb,
    const float* __restrict__ w_z, const float* __restrict__ b_z,
    float* __restrict__ out)
{
    __shared__ float s_x[64][132];
    __shared__ float s_w[8][128];
    const int t = threadIdx.x;
    const int i_idx = blockIdx.y;
    const int j0 = blockIdx.x * 64;

    // gather X from channel-group-major layout (coalesced per cg)
    #pragma unroll
    for (int l = 0; l < 8; l++) {
        const int idx = t + l * 256;     // 0..2047
        const int cg = idx >> 6, j = idx & 63;
        const float4 v = d_X4[(size_t)cg * 262144 + (size_t)i_idx * 512 + (j0 + j)];
        *(float4*)&s_x[j][cg * 4] = v;
    }
    __syncthreads();
    ln_rows(s_x, lng, lnb);
    __syncthreads();

    const int tx = t & 31, ty = t >> 5;
    float acc[8][4];
    #pragma unroll
    for (int pi = 0; pi < 8; pi++)
        #pragma unroll
        for (int ci = 0; ci < 4; ci++) acc[pi][ci] = 0.f;

    #pragma unroll 1
    for (int k0 = 0; k0 < 128; k0 += 8) {
        __syncthreads();
        #pragma unroll
        for (int l = 0; l < 4; l++) {
            const int idx = t + l * 256;
            const int rk = idx >> 7, c = idx & 127;
            s_w[rk][c] = w_z[(k0 + rk) * 128 + c];
        }
        __syncthreads();
        #pragma unroll
        for (int kk = 0; kk < 8; kk++) {
            const float4 wv = *(const float4*)&s_w[kk][tx * 4];
            #pragma unroll
            for (int pi = 0; pi < 8; pi++) {
                const float av = s_x[ty + 8 * pi][k0 + kk];
                acc[pi][0] = fmaf(av, wv.x, acc[pi][0]);
                acc[pi][1] = fmaf(av, wv.y, acc[pi][1]);
                acc[pi][2] = fmaf(av, wv.z, acc[pi][2]);
                acc[pi][3] = fmaf(av, wv.w, acc[pi][3]);
            }
        }
    }

    const float4 bz = *(const float4*)&b_z[tx * 4];
    #pragma unroll
    for (int pi = 0; pi < 8; pi++) {
        const int r = ty + 8 * pi;
        const size_t pos = (size_t)i_idx * 512 + (j0 + r);
        const float4 g4 = *(const float4*)&d_G[pos * 128 + tx * 4];
        float4 o;
        o.x = (acc[pi][0] + bz.x) * g4.x;
        o.y = (acc[pi][1] + bz.y) * g4.y;
        o.z = (acc[pi][2] + bz.z) * g4.z;
        o.w = (acc[pi][3] + bz.w) * g4.w;
        *(float4*)&out[pos * 128 + tx * 4] = o;
    }
}

extern "C" void kernel_launch(void* const* d_in, const int* in_sizes, int n_in,
                              void* d_out, int out_size)
{
    const float* z       = (const float*)d_in[0];
    const float* mask    = (const float*)d_in[1];
    const float* w_ag    = (const float*)d_in[2];
    const float* b_ag    = (const float*)d_in[3];
    const float* w_ap    = (const float*)d_in[4];
    const float* b_ap    = (const float*)d_in[5];
    const float* w_bg    = (const float*)d_in[6];
    const float* b_bg    = (const float*)d_in[7];
    const float* w_bp    = (const float*)d_in[8];
    const float* b_bp    = (const float*)d_in[9];
    const float* w_g     = (const float*)d_in[10];
    const float* b_g     = (const float*)d_in[11];
    const float* w_z     = (const float*)d_in[12];
    const float* b_z     = (const float*)d_in[13];
    const float* ln_in_g = (const float*)d_in[14];
    const float* ln_in_b = (const float*)d_in[15];
    const float* ln_out_g= (const float*)d_in[16];
    const float* ln_out_b= (const float*)d_in[17];

    kP<<<4096, 256>>>(z, mask, w_ag, b_ag, w_ap, b_ap, w_bg, b_bg, w_bp, b_bp,
                      w_g, b_g, ln_in_g, ln_in_b);
    kE<<<dim3(8, 8, 32), 256>>>();
    kF<<<dim3(8, 512), 256>>>(ln_out_g, ln_out_b, w_z, b_z, (float*)d_out);
}

// round 2
// speedup vs baseline: 2.6350x; 2.6350x over previous
#include <cuda_runtime.h>
#include <cstdint>

// TriangleMultiplicativeUpdate (outgoing), B=1, N=512, C=128.
// tf32 mma.sync (m16n8k8) version.
// kP: LN + 5 projections (pairs fused) -> per-channel planes a[c][pos], b[c][pos], g natural
// kE: 128 per-channel GEMMs X_c = A_c @ B_c^T  (512x512x512 each)
// kF: gather X, LN, @w_z + b_z, * g

#define NPOS 262144   // 512*512

// Scratch planes: [c][pos], pos = i*512+k (or i*512+j for X)
__device__ float d_A[128 * NPOS];   // 128 MB
__device__ float d_B[128 * NPOS];   // 128 MB
__device__ float d_X[128 * NPOS];   // 128 MB
__device__ float d_G[NPOS * 128];   // 128 MB, natural [pos][c]

__device__ __forceinline__ float sigf(float x) { return 1.0f / (1.0f + __expf(-x)); }

// round-to-nearest tf32 (keeps value as valid fp32 with low mantissa zeroed)
__device__ __forceinline__ float tf32r(float x) {
    unsigned u;
    asm("cvt.rna.tf32.f32 %0, %1;" : "=r"(u) : "f"(x));
    return __uint_as_float(u);
}

__device__ __forceinline__ void mma8(float* d, const unsigned* a, const unsigned* b) {
    asm volatile(
        "mma.sync.aligned.m16n8k8.row.col.f32.tf32.tf32.f32 "
        "{%0,%1,%2,%3}, {%4,%5,%6,%7}, {%8,%9}, {%0,%1,%2,%3};\n"
        : "+f"(d[0]), "+f"(d[1]), "+f"(d[2]), "+f"(d[3])
        : "r"(a[0]), "r"(a[1]), "r"(a[2]), "r"(a[3]), "r"(b[0]), "r"(b[1]));
}

// LayerNorm rows of 128 cols in smem (stride 132). 8 warps, rpw rows per warp.
// Output is tf32-rounded (all LN outputs feed MMAs only).
__device__ __forceinline__ void ln_rows(float* s, const float* __restrict__ g,
                                        const float* __restrict__ b, int rpw) {
    const int warp = threadIdx.x >> 5, lane = threadIdx.x & 31;
    const float g0 = g[lane], g1 = g[lane + 32], g2 = g[lane + 64], g3 = g[lane + 96];
    const float b0 = b[lane], b1 = b[lane + 32], b2 = b[lane + 64], b3 = b[lane + 96];
    #pragma unroll 1
    for (int rr = 0; rr < rpw; rr++) {
        const int r = warp * rpw + rr;
        float* row = s + r * 132;
        float v0 = row[lane], v1 = row[lane + 32], v2 = row[lane + 64], v3 = row[lane + 96];
        float sm = (v0 + v1) + (v2 + v3);
        float sq = fmaf(v0, v0, fmaf(v1, v1, fmaf(v2, v2, v3 * v3)));
        #pragma unroll
        for (int o = 16; o > 0; o >>= 1) {
            sm += __shfl_xor_sync(0xffffffffu, sm, o);
            sq += __shfl_xor_sync(0xffffffffu, sq, o);
        }
        const float mean = sm * 0.0078125f;
        const float var  = fmaf(-mean, mean, sq * 0.0078125f);
        const float rs   = rsqrtf(var + 1e-5f);
        row[lane]      = tf32r(fmaf((v0 - mean) * rs, g0, b0));
        row[lane + 32] = tf32r(fmaf((v1 - mean) * rs, g1, b1));
        row[lane + 64] = tf32r(fmaf((v2 - mean) * rs, g2, b2));
        row[lane + 96] = tf32r(fmaf((v3 - mean) * rs, g3, b3));
    }
}

// ---------------- kP ---------------------------------------------------------
// grid (3, 4096): x = slice (0:a-pair, 1:b-pair, 2:g), y = pos-block.
// Pair slices: 64 positions; warps 0-3 gemm gate, warps 4-7 gemm proj (64x128 each),
// combine via smem, transposed store to per-channel plane.
// g slice: 128 positions (only y<2048 active); warp-group g handles rows g*64..+63.
__global__ __launch_bounds__(256) void kP(
    const float* __restrict__ z,    const float* __restrict__ mask,
    const float* __restrict__ w_ag, const float* __restrict__ b_ag,
    const float* __restrict__ w_ap, const float* __restrict__ b_ap,
    const float* __restrict__ w_bg, const float* __restrict__ b_bg,
    const float* __restrict__ w_bp, const float* __restrict__ b_bp,
    const float* __restrict__ w_g,  const float* __restrict__ b_g,
    const float* __restrict__ lng,  const float* __restrict__ lnb)
{
    extern __shared__ float sm[];
    float* sZ = sm;                       // [128][132]
    float* sW = sm + 128 * 132;           // [2][16][136]

    const int t = threadIdx.x, lane = t & 31, warp = t >> 5;
    const int gw = warp >> 2, lw = warp & 3;
    const int slice = blockIdx.x;
    const int xb = blockIdx.y;
    const bool gmode = (slice == 2);
    if (gmode && xb >= 2048) return;

    const int pos0 = gmode ? xb * 128 : xb * 64;
    const int nrows = gmode ? 128 : 64;

    // load z tile, LN (+tf32 round)
    for (int idx = t * 4; idx < nrows * 128; idx += 1024) {
        float4 v = *(const float4*)&z[(size_t)pos0 * 128 + idx];
        *(float4*)&sZ[(idx >> 7) * 132 + (idx & 127)] = v;
    }
    __syncthreads();
    ln_rows(sZ, lng, lnb, nrows >> 3);
    __syncthreads();

    const float* wsrc0 = gmode ? w_g : (slice ? w_bg : w_ag);
    const float* wsrc1 = gmode ? w_g : (slice ? w_bp : w_ap);
    const int rbase = gmode ? gw * 64 : 0;

    float acc[4][4][4] = {};

    #pragma unroll 1
    for (int k0 = 0; k0 < 128; k0 += 16) {
        __syncthreads();
        #pragma unroll
        for (int l = 0; l < 16; l++) {
            const float* wp = (l < 8) ? wsrc0 : wsrc1;
            const int s = l >> 3;
            const int rk = (2 * l + (t >> 7)) & 15;
            const int c = t & 127;
            sW[(s * 16 + rk) * 136 + c] = tf32r(wp[(k0 + rk) * 128 + c]);
        }
        __syncthreads();
        #pragma unroll
        for (int kh = 0; kh < 2; kh++) {
            const int kk = kh * 8;
            unsigned af[4][4], bf[4][2];
            #pragma unroll
            for (int mt = 0; mt < 4; mt++) {
                const int r = rbase + mt * 16 + (lane >> 2);
                const int c = k0 + kk + (lane & 3);
                af[mt][0] = __float_as_uint(sZ[r * 132 + c]);
                af[mt][1] = __float_as_uint(sZ[(r + 8) * 132 + c]);
                af[mt][2] = __float_as_uint(sZ[r * 132 + c + 4]);
                af[mt][3] = __float_as_uint(sZ[(r + 8) * 132 + c + 4]);
            }
            const float* wsm = sW + gw * 16 * 136;
            #pragma unroll
            for (int nt = 0; nt < 4; nt++) {
                const int n = lw * 32 + nt * 8 + (lane >> 2);
                bf[nt][0] = __float_as_uint(wsm[(kk + (lane & 3)) * 136 + n]);
                bf[nt][1] = __float_as_uint(wsm[(kk + (lane & 3) + 4) * 136 + n]);
            }
            #pragma unroll
            for (int mt = 0; mt < 4; mt++)
                #pragma unroll
                for (int nt = 0; nt < 4; nt++)
                    mma8(acc[mt][nt], af[mt], bf[nt]);
        }
    }
    __syncthreads();

    if (!gmode) {
        float* cb = sZ + 64 * 132;        // 64x132 combine buffer
        const float* bias0 = slice ? b_bg : b_ag;
        const float* bias1 = slice ? b_bp : b_ap;
        if (gw == 0) {
            #pragma unroll
            for (int mt = 0; mt < 4; mt++)
                #pragma unroll
                for (int nt = 0; nt < 4; nt++) {
                    const int r0 = mt * 16 + (lane >> 2);
                    const int c0 = lw * 32 + nt * 8 + (lane & 3) * 2;
                    const float bb0 = bias0[c0], bb1 = bias0[c0 + 1];
                    cb[r0 * 132 + c0]           = sigf(acc[mt][nt][0] + bb0);
                    cb[r0 * 132 + c0 + 1]       = sigf(acc[mt][nt][1] + bb1);
                    cb[(r0 + 8) * 132 + c0]     = sigf(acc[mt][nt][2] + bb0);
                    cb[(r0 + 8) * 132 + c0 + 1] = sigf(acc[mt][nt][3] + bb1);
                }
        }
        __syncthreads();
        if (gw == 1) {
            #pragma unroll
            for (int mt = 0; mt < 4; mt++)
                #pragma unroll
                for (int nt = 0; nt < 4; nt++) {
                    const int r0 = mt * 16 + (lane >> 2);
                    const int c0 = lw * 32 + nt * 8 + (lane & 3) * 2;
                    const float bb0 = bias1[c0], bb1 = bias1[c0 + 1];
                    const float m0 = mask[pos0 + r0], m1 = mask[pos0 + r0 + 8];
                    cb[r0 * 132 + c0]           = tf32r(m0 * cb[r0 * 132 + c0]           * (acc[mt][nt][0] + bb0));
                    cb[r0 * 132 + c0 + 1]       = tf32r(m0 * cb[r0 * 132 + c0 + 1]       * (acc[mt][nt][1] + bb1));
                    cb[(r0 + 8) * 132 + c0]     = tf32r(m1 * cb[(r0 + 8) * 132 + c0]     * (acc[mt][nt][2] + bb0));
                    cb[(r0 + 8) * 132 + c0 + 1] = tf32r(m1 * cb[(r0 + 8) * 132 + c0 + 1] * (acc[mt][nt][3] + bb1));
                }
        }
        __syncthreads();
        float* plane = slice ? d_B : d_A;
        #pragma unroll
        for (int l = 0; l < 32; l++) {
            const int c = l * 4 + (t >> 6);
            const int p = t & 63;
            plane[(size_t)c * NPOS + pos0 + p] = cb[p * 132 + c];
        }
    } else {
        #pragma unroll
        for (int mt = 0; mt < 4; mt++)
            #pragma unroll
            for (int nt = 0; nt < 4; nt++) {
                const int r = rbase + mt * 16 + (lane >> 2);
                const int c0 = lw * 32 + nt * 8 + (lane & 3) * 2;
                const float bb0 = b_g[c0], bb1 = b_g[c0 + 1];
                float2 v0 = make_float2(sigf(acc[mt][nt][0] + bb0), sigf(acc[mt][nt][1] + bb1));
                float2 v1 = make_float2(sigf(acc[mt][nt][2] + bb0), sigf(acc[mt][nt][3] + bb1));
                *(float2*)&d_G[(size_t)(pos0 + r) * 128 + c0] = v0;
                *(float2*)&d_G[(size_t)(pos0 + r + 8) * 128 + c0] = v1;
            }
    }
}

// ---------------- kE: per-channel GEMM X_c = A_c @ B_c^T --------------------
// grid (4, 4, 128): 128x128 output tile per block, K=512. 16 consecutive blocks
// share one channel's planes (L2 reuse).
__global__ __launch_bounds__(256) void kE()
{
    __shared__ float sA[128 * 20];
    __shared__ float sB[128 * 20];
    const int t = threadIdx.x, lane = t & 31, warp = t >> 5;
    const int wy = warp >> 2, lw = warp & 3;
    const int j0 = blockIdx.x * 128, i0 = blockIdx.y * 128, ch = blockIdx.z;
    const float* __restrict__ Ap = d_A + (size_t)ch * NPOS;
    const float* __restrict__ Bp = d_B + (size_t)ch * NPOS;

    float acc[4][4][4] = {};

    #pragma unroll 1
    for (int kt = 0; kt < 512; kt += 16) {
        __syncthreads();
        #pragma unroll
        for (int l = 0; l < 2; l++) {
            const int f = t + l * 256;            // float4 id 0..511
            const int r = f >> 2, c4 = (f & 3) * 4;
            *(float4*)&sA[r * 20 + c4] = *(const float4*)&Ap[(size_t)(i0 + r) * 512 + kt + c4];
            *(float4*)&sB[r * 20 + c4] = *(const float4*)&Bp[(size_t)(j0 + r) * 512 + kt + c4];
        }
        __syncthreads();
        #pragma unroll
        for (int kh = 0; kh < 2; kh++) {
            const int kk = kh * 8;
            unsigned af[4][4], bf[4][2];
            #pragma unroll
            for (int mt = 0; mt < 4; mt++) {
                const int r = wy * 64 + mt * 16 + (lane >> 2);
                const int c = kk + (lane & 3);
                af[mt][0] = __float_as_uint(sA[r * 20 + c]);
                af[mt][1] = __float_as_uint(sA[(r + 8) * 20 + c]);
                af[mt][2] = __float_as_uint(sA[r * 20 + c + 4]);
                af[mt][3] = __float_as_uint(sA[(r + 8) * 20 + c + 4]);
            }
            #pragma unroll
            for (int nt = 0; nt < 4; nt++) {
                const int n = lw * 32 + nt * 8 + (lane >> 2);
                bf[nt][0] = __float_as_uint(sB[n * 20 + kk + (lane & 3)]);
                bf[nt][1] = __float_as_uint(sB[n * 20 + kk + (lane & 3) + 4]);
            }
            #pragma unroll
            for (int mt = 0; mt < 4; mt++)
                #pragma unroll
                for (int nt = 0; nt < 4; nt++)
                    mma8(acc[mt][nt], af[mt], bf[nt]);
        }
    }

    float* Xp = d_X + (size_t)ch * NPOS;
    #pragma unroll
    for (int mt = 0; mt < 4; mt++)
        #pragma unroll
        for (int nt = 0; nt < 4; nt++) {
            const int r = i0 + wy * 64 + mt * 16 + (lane >> 2);
            const int jj = j0 + lw * 32 + nt * 8 + (lane & 3) * 2;
            *(float2*)&Xp[(size_t)r * 512 + jj]       = make_float2(acc[mt][nt][0], acc[mt][nt][1]);
            *(float2*)&Xp[(size_t)(r + 8) * 512 + jj] = make_float2(acc[mt][nt][2], acc[mt][nt][3]);
        }
}

// ---------------- kF: LN(X) @ w_z + b_z, * g ---------------------------------
// grid 4096: 64 positions per block. Warp grid 2x4: warp tile 32x32.
__global__ __launch_bounds__(256) void kF(
    const float* __restrict__ lng, const float* __restrict__ lnb,
    const float* __restrict__ w_z, const float* __restrict__ b_z,
    float* __restrict__ out)
{
    __shared__ float sX[64 * 132];
    __shared__ float sW[16 * 136];
    const int t = threadIdx.x, lane = t & 31, warp = t >> 5;
    const int wy = warp >> 2, lw = warp & 3;
    const int pos0 = blockIdx.x * 64;

    // gather X (per-channel planes -> row-major 64x128)
    #pragma unroll
    for (int l = 0; l < 32; l++) {
        const int c = l * 4 + (t >> 6);
        const int p = t & 63;
        sX[p * 132 + c] = d_X[(size_t)c * NPOS + pos0 + p];
    }
    __syncthreads();
    ln_rows(sX, lng, lnb, 8);
    __syncthreads();

    float acc[2][4][4] = {};

    #pragma unroll 1
    for (int k0 = 0; k0 < 128; k0 += 16) {
        __syncthreads();
        #pragma unroll
        for (int l = 0; l < 8; l++) {
            const int rk = (2 * l + (t >> 7)) & 15;
            const int c = t & 127;
            sW[rk * 136 + c] = tf32r(w_z[(k0 + rk) * 128 + c]);
        }
        __syncthreads();
        #pragma unroll
        for (int kh = 0; kh < 2; kh++) {
            const int kk = kh * 8;
            unsigned af[2][4], bf[4][2];
            #pragma unroll
            for (int mt = 0; mt < 2; mt++) {
                const int r = wy * 32 + mt * 16 + (lane >> 2);
                const int c = k0 + kk + (lane & 3);
                af[mt][0] = __float_as_uint(sX[r * 132 + c]);
                af[mt][1] = __float_as_uint(sX[(r + 8) * 132 + c]);
                af[mt][2] = __float_as_uint(sX[r * 132 + c + 4]);
                af[mt][3] = __float_as_uint(sX[(r + 8) * 132 + c + 4]);
            }
            #pragma unroll
            for (int nt = 0; nt < 4; nt++) {
                const int n = lw * 32 + nt * 8 + (lane >> 2);
                bf[nt][0] = __float_as_uint(sW[(kk + (lane & 3)) * 136 + n]);
                bf[nt][1] = __float_as_uint(sW[(kk + (lane & 3) + 4) * 136 + n]);
            }
            #pragma unroll
            for (int mt = 0; mt < 2; mt++)
                #pragma unroll
                for (int nt = 0; nt < 4; nt++)
                    mma8(acc[mt][nt], af[mt], bf[nt]);
        }
    }

    #pragma unroll
    for (int mt = 0; mt < 2; mt++)
        #pragma unroll
        for (int nt = 0; nt < 4; nt++) {
            const int r = wy * 32 + mt * 16 + (lane >> 2);
            const int c0 = lw * 32 + nt * 8 + (lane & 3) * 2;
            const float bb0 = b_z[c0], bb1 = b_z[c0 + 1];
            const size_t p0 = (size_t)(pos0 + r) * 128 + c0;
            const size_t p1 = (size_t)(pos0 + r + 8) * 128 + c0;
            const float2 g0 = *(const float2*)&d_G[p0];
            const float2 g1 = *(const float2*)&d_G[p1];
            float2 o0 = make_float2((acc[mt][nt][0] + bb0) * g0.x, (acc[mt][nt][1] + bb1) * g0.y);
            float2 o1 = make_float2((acc[mt][nt][2] + bb0) * g1.x, (acc[mt][nt][3] + bb1) * g1.y);
            *(float2*)&out[p0] = o0;
            *(float2*)&out[p1] = o1;
        }
}

extern "C" void kernel_launch(void* const* d_in, const int* in_sizes, int n_in,
                              void* d_out, int out_size)
{
    const float* z        = (const float*)d_in[0];
    const float* mask     = (const float*)d_in[1];
    const float* w_ag     = (const float*)d_in[2];
    const float* b_ag     = (const float*)d_in[3];
    const float* w_ap     = (const float*)d_in[4];
    const float* b_ap     = (const float*)d_in[5];
    const float* w_bg     = (const float*)d_in[6];
    const float* b_bg     = (const float*)d_in[7];
    const float* w_bp     = (const float*)d_in[8];
    const float* b_bp     = (const float*)d_in[9];
    const float* w_g      = (const float*)d_in[10];
    const float* b_g      = (const float*)d_in[11];
    const float* w_z      = (const float*)d_in[12];
    const float* b_z      = (const float*)d_in[13];
    const float* ln_in_g  = (const float*)d_in[14];
    const float* ln_in_b  = (const float*)d_in[15];
    const float* ln_out_g = (const float*)d_in[16];
    const float* ln_out_b = (const float*)d_in[17];

    const int KP_SMEM = (128 * 132 + 2 * 16 * 136) * 4;   // 84992 bytes
    cudaFuncSetAttribute(kP, cudaFuncAttributeMaxDynamicSharedMemorySize, KP_SMEM);

    kP<<<dim3(3, 4096), 256, KP_SMEM>>>(z, mask, w_ag, b_ag, w_ap, b_ap,
                                        w_bg, b_bg, w_bp, b_bp, w_g, b_g,
                                        ln_in_g, ln_in_b);
    kE<<<dim3(4, 4, 128), 256>>>();
    kF<<<4096, 256>>>(ln_out_g, ln_out_b, w_z, b_z, (float*)d_out);
}

// round 3
// speedup vs baseline: 4.2288x; 1.6048x over previous
#include <cuda_runtime.h>
#include <cuda_fp16.h>
#include <cstdint>

// TriangleMultiplicativeUpdate (outgoing), B=1, N=512, C=128.  fp16 mma.sync m16n8k16.
// kW: transpose+convert 6 weight matrices -> d_Wt[w][n][k] half (one-time per launch)
// kP: LN once + all 5 projections -> half planes d_Ah/d_Bh [c][pos], d_G fp32 [pos][c]
// kE: 128 per-channel GEMMs X_c = A_c @ B_c^T (fp32 out)
// kF: gather X, LN, @w_z + b_z, * g

#define NPOS 262144
#define SZS  136          // smem row stride in halfs (kP/kF)
#define KES  72           // smem row stride in halfs (kE)

__device__ __half d_Wt[6 * 16384];          // [w][n][k]
__device__ __half d_Ah[(size_t)128 * NPOS]; // 64 MB
__device__ __half d_Bh[(size_t)128 * NPOS]; // 64 MB
__device__ float  d_X [(size_t)128 * NPOS]; // 128 MB  [c][i*512+j]
__device__ float  d_G [(size_t)NPOS * 128]; // 128 MB  [pos][c]

__device__ __forceinline__ float sigf(float x) { return 1.0f / (1.0f + __expf(-x)); }

__device__ __forceinline__ void mma16(float* d, const unsigned* a, const unsigned* b) {
    asm volatile(
        "mma.sync.aligned.m16n8k16.row.col.f32.f16.f16.f32 "
        "{%0,%1,%2,%3}, {%4,%5,%6,%7}, {%8,%9}, {%0,%1,%2,%3};\n"
        : "+f"(d[0]), "+f"(d[1]), "+f"(d[2]), "+f"(d[3])
        : "r"(a[0]), "r"(a[1]), "r"(a[2]), "r"(a[3]), "r"(b[0]), "r"(b[1]));
}

__device__ __forceinline__ void ldsm4(unsigned* r, const __half* p) {
    unsigned addr = (unsigned)__cvta_generic_to_shared(p);
    asm volatile("ldmatrix.sync.aligned.m8n8.x4.shared.b16 {%0,%1,%2,%3}, [%4];"
                 : "=r"(r[0]), "=r"(r[1]), "=r"(r[2]), "=r"(r[3]) : "r"(addr));
}

// ---------------- kW: weight transpose+convert ------------------------------
__global__ __launch_bounds__(256) void kW(
    const float* __restrict__ w_ag, const float* __restrict__ w_ap,
    const float* __restrict__ w_bg, const float* __restrict__ w_bp,
    const float* __restrict__ w_g,  const float* __restrict__ w_z)
{
    __shared__ float s[128 * 132];
    const float* srcs[6] = {w_ag, w_ap, w_bg, w_bp, w_g, w_z};
    const float* w = srcs[blockIdx.x];
    const int t = threadIdx.x;
    #pragma unroll
    for (int l = 0; l < 64; l++) {
        const int idx = t + l * 256;
        s[(idx >> 7) * 132 + (idx & 127)] = w[idx];   // [k][n]
    }
    __syncthreads();
    __half* dst = d_Wt + blockIdx.x * 16384;
    #pragma unroll
    for (int l = 0; l < 64; l++) {
        const int idx = t + l * 256;                  // idx = n*128 + k
        dst[idx] = __float2half_rn(s[(idx & 127) * 132 + (idx >> 7)]);
    }
}

// ---------------- kP ---------------------------------------------------------
// 512 threads, 128 rows per block (2048 blocks). Warp grid 4(M)x4(N): warp tile 32x32.
__device__ __forceinline__ void gemmP(
    const __half* __restrict__ wt, __half* sW, const __half* sZ,
    float acc[2][4][4], int t, int wy, int lw,
    int aRow, int aCol, int bRow, int bCol)
{
    __syncthreads();
    const uint4* src = (const uint4*)wt;
    #pragma unroll
    for (int l = 0; l < 4; l++) {
        const int idx = t + l * 512;                 // 2048 uint4
        const int n = idx >> 4, k8 = (idx & 15) * 8;
        *(uint4*)&sW[n * SZS + k8] = src[idx];
    }
    __syncthreads();
    #pragma unroll
    for (int k0 = 0; k0 < 128; k0 += 16) {
        unsigned af[2][4], bf[2][4];
        #pragma unroll
        for (int mt = 0; mt < 2; mt++)
            ldsm4(af[mt], sZ + (wy * 32 + mt * 16 + aRow) * SZS + k0 + aCol);
        #pragma unroll
        for (int p = 0; p < 2; p++)
            ldsm4(bf[p], sW + (lw * 32 + p * 16 + bRow) * SZS + k0 + bCol);
        #pragma unroll
        for (int mt = 0; mt < 2; mt++)
            #pragma unroll
            for (int nt = 0; nt < 4; nt++)
                mma16(acc[mt][nt], af[mt], &bf[nt >> 1][(nt & 1) * 2]);
    }
}

__global__ __launch_bounds__(512) void kP(
    const float* __restrict__ z,    const float* __restrict__ mask,
    const float* __restrict__ b_ag, const float* __restrict__ b_ap,
    const float* __restrict__ b_bg, const float* __restrict__ b_bp,
    const float* __restrict__ b_g,
    const float* __restrict__ lng,  const float* __restrict__ lnb)
{
    extern __shared__ __half sh[];
    __half* sZ = sh;                 // [128][SZS]
    __half* sW = sh + 128 * SZS;     // [128][SZS], weights / staging
    const int t = threadIdx.x, lane = t & 31, warp = t >> 5;
    const int wy = warp >> 2, lw = warp & 3;
    const int pos0 = blockIdx.x * 128;

    // LayerNorm 128 rows straight from global -> half smem
    {
        const float g0 = lng[lane], g1 = lng[lane + 32], g2 = lng[lane + 64], g3 = lng[lane + 96];
        const float bb0 = lnb[lane], bb1 = lnb[lane + 32], bb2 = lnb[lane + 64], bb3 = lnb[lane + 96];
        #pragma unroll 1
        for (int rr = 0; rr < 8; rr++) {
            const int r = warp * 8 + rr;
            const float* zr = z + (size_t)(pos0 + r) * 128;
            float v0 = zr[lane], v1 = zr[lane + 32], v2 = zr[lane + 64], v3 = zr[lane + 96];
            float sm = (v0 + v1) + (v2 + v3);
            float sq = fmaf(v0, v0, fmaf(v1, v1, fmaf(v2, v2, v3 * v3)));
            #pragma unroll
            for (int o = 16; o > 0; o >>= 1) {
                sm += __shfl_xor_sync(0xffffffffu, sm, o);
                sq += __shfl_xor_sync(0xffffffffu, sq, o);
            }
            const float mean = sm * 0.0078125f;
            const float var  = fmaf(-mean, mean, sq * 0.0078125f);
            const float rs   = rsqrtf(var + 1e-5f);
            sZ[r * SZS + lane]      = __float2half_rn(fmaf((v0 - mean) * rs, g0, bb0));
            sZ[r * SZS + lane + 32] = __float2half_rn(fmaf((v1 - mean) * rs, g1, bb1));
            sZ[r * SZS + lane + 64] = __float2half_rn(fmaf((v2 - mean) * rs, g2, bb2));
            sZ[r * SZS + lane + 96] = __float2half_rn(fmaf((v3 - mean) * rs, g3, bb3));
        }
    }

    const int aRow = (lane & 7) + ((lane >> 3) & 1) * 8;
    const int aCol = (lane >> 4) * 8;
    const int bRow = (lane & 7) + ((lane >> 4) & 1) * 8;
    const int bCol = ((lane >> 3) & 1) * 8;
    const int rB = wy * 32 + (lane >> 2);             // acc row base
    const int cB = lw * 32 + (lane & 3) * 2;          // acc col base

    // ---- pair A: gate = sigmoid(zn@w_ag+b), a = mask*gate*(zn@w_ap+b) ----
    // ---- pair B: same with bg/bp ----
    #pragma unroll 1
    for (int pair = 0; pair < 2; pair++) {
        const float* biasG = pair ? b_bg : b_ag;
        const float* biasP = pair ? b_bp : b_ap;
        __half* plane = pair ? d_Bh : d_Ah;

        float accg[2][4][4] = {};
        gemmP(d_Wt + (pair * 2 + 0) * 16384, sW, sZ, accg, t, wy, lw, aRow, aCol, bRow, bCol);
        float gate[2][4][4];
        #pragma unroll
        for (int mt = 0; mt < 2; mt++)
            #pragma unroll
            for (int nt = 0; nt < 4; nt++) {
                const int c = cB + nt * 8;
                const float bg0 = biasG[c], bg1 = biasG[c + 1];
                gate[mt][nt][0] = sigf(accg[mt][nt][0] + bg0);
                gate[mt][nt][1] = sigf(accg[mt][nt][1] + bg1);
                gate[mt][nt][2] = sigf(accg[mt][nt][2] + bg0);
                gate[mt][nt][3] = sigf(accg[mt][nt][3] + bg1);
            }
        float accp[2][4][4] = {};
        gemmP(d_Wt + (pair * 2 + 1) * 16384, sW, sZ, accp, t, wy, lw, aRow, aCol, bRow, bCol);
        __syncthreads();   // done reading sW as weights; reuse as staging
        #pragma unroll
        for (int mt = 0; mt < 2; mt++) {
            const int r = rB + mt * 16;
            const float m0 = mask[pos0 + r], m1 = mask[pos0 + r + 8];
            #pragma unroll
            for (int nt = 0; nt < 4; nt++) {
                const int c = cB + nt * 8;
                const float bp0 = biasP[c], bp1 = biasP[c + 1];
                __half2 v0, v1;
                v0.x = __float2half_rn(m0 * gate[mt][nt][0] * (accp[mt][nt][0] + bp0));
                v0.y = __float2half_rn(m0 * gate[mt][nt][1] * (accp[mt][nt][1] + bp1));
                v1.x = __float2half_rn(m1 * gate[mt][nt][2] * (accp[mt][nt][2] + bp0));
                v1.y = __float2half_rn(m1 * gate[mt][nt][3] * (accp[mt][nt][3] + bp1));
                *(__half2*)&sW[r * SZS + c]       = v0;
                *(__half2*)&sW[(r + 8) * SZS + c] = v1;
            }
        }
        __syncthreads();
        // transposed flush: [r][c] -> plane[c][pos0+r]
        #pragma unroll
        for (int l = 0; l < 32; l++) {
            const int idx = t + l * 512;
            const int c = idx >> 7, p = idx & 127;
            plane[(size_t)c * NPOS + pos0 + p] = sW[p * SZS + c];
        }
    }

    // ---- g = sigmoid(zn@w_g + b_g), fp32 natural layout ----
    {
        float accq[2][4][4] = {};
        gemmP(d_Wt + 4 * 16384, sW, sZ, accq, t, wy, lw, aRow, aCol, bRow, bCol);
        #pragma unroll
        for (int mt = 0; mt < 2; mt++) {
            const int r = rB + mt * 16;
            #pragma unroll
            for (int nt = 0; nt < 4; nt++) {
                const int c = cB + nt * 8;
                const float bg0 = b_g[c], bg1 = b_g[c + 1];
                *(float2*)&d_G[(size_t)(pos0 + r) * 128 + c] =
                    make_float2(sigf(accq[mt][nt][0] + bg0), sigf(accq[mt][nt][1] + bg1));
                *(float2*)&d_G[(size_t)(pos0 + r + 8) * 128 + c] =
                    make_float2(sigf(accq[mt][nt][2] + bg0), sigf(accq[mt][nt][3] + bg1));
            }
        }
    }
}

// ---------------- kE: per-channel GEMM X_c = A_c @ B_c^T --------------------
__global__ __launch_bounds__(256) void kE()
{
    __shared__ __half sA[128 * KES];
    __shared__ __half sB[128 * KES];
    const int t = threadIdx.x, lane = t & 31, warp = t >> 5;
    const int wy = warp >> 2, lw = warp & 3;
    const int j0 = blockIdx.x * 128, i0 = blockIdx.y * 128, ch = blockIdx.z;
    const __half* __restrict__ Ap = d_Ah + (size_t)ch * NPOS;
    const __half* __restrict__ Bp = d_Bh + (size_t)ch * NPOS;

    const int aRow = (lane & 7) + ((lane >> 3) & 1) * 8;
    const int aCol = (lane >> 4) * 8;
    const int bRow = (lane & 7) + ((lane >> 4) & 1) * 8;
    const int bCol = ((lane >> 3) & 1) * 8;

    float acc[4][4][4] = {};

    #pragma unroll 1
    for (int kt = 0; kt < 512; kt += 64) {
        __syncthreads();
        #pragma unroll
        for (int l = 0; l < 4; l++) {
            const int idx = t + l * 256;
            const int r = idx >> 3, k8 = (idx & 7) * 8;
            *(uint4*)&sA[r * KES + k8] = *(const uint4*)&Ap[(size_t)(i0 + r) * 512 + kt + k8];
            *(uint4*)&sB[r * KES + k8] = *(const uint4*)&Bp[(size_t)(j0 + r) * 512 + kt + k8];
        }
        __syncthreads();
        #pragma unroll
        for (int kk = 0; kk < 64; kk += 16) {
            unsigned af[4][4], bf[2][4];
            #pragma unroll
            for (int mt = 0; mt < 4; mt++)
                ldsm4(af[mt], sA + (wy * 64 + mt * 16 + aRow) * KES + kk + aCol);
            #pragma unroll
            for (int p = 0; p < 2; p++)
                ldsm4(bf[p], sB + (lw * 32 + p * 16 + bRow) * KES + kk + bCol);
            #pragma unroll
            for (int mt = 0; mt < 4; mt++)
                #pragma unroll
                for (int nt = 0; nt < 4; nt++)
                    mma16(acc[mt][nt], af[mt], &bf[nt >> 1][(nt & 1) * 2]);
        }
    }

    float* Xp = d_X + (size_t)ch * NPOS;
    #pragma unroll
    for (int mt = 0; mt < 4; mt++)
        #pragma unroll
        for (int nt = 0; nt < 4; nt++) {
            const int r = i0 + wy * 64 + mt * 16 + (lane >> 2);
            const int jj = j0 + lw * 32 + nt * 8 + (lane & 3) * 2;
            *(float2*)&Xp[(size_t)r * 512 + jj]       = make_float2(acc[mt][nt][0], acc[mt][nt][1]);
            *(float2*)&Xp[(size_t)(r + 8) * 512 + jj] = make_float2(acc[mt][nt][2], acc[mt][nt][3]);
        }
}

// ---------------- kF: LN(X) @ w_z + b_z, * g ---------------------------------
__global__ __launch_bounds__(256) void kF(
    const float* __restrict__ lng, const float* __restrict__ lnb,
    const float* __restrict__ b_z, float* __restrict__ out)
{
    extern __shared__ char smf[];
    float*  sXf = (float*)smf;                          // [64][132] fp32
    __half* sX  = (__half*)(smf + 64 * 132 * 4);        // [64][SZS]
    __half* sW  = (__half*)(smf + 64 * 132 * 4 + 64 * SZS * 2);  // [128][SZS]
    const int t = threadIdx.x, lane = t & 31, warp = t >> 5;
    const int wy = warp >> 2, lw = warp & 3;
    const int pos0 = blockIdx.x * 64;

    // gather X planes -> row-major fp32
    #pragma unroll
    for (int l = 0; l < 32; l++) {
        const int c = l * 4 + (t >> 6);
        const int p = t & 63;
        sXf[p * 132 + c] = d_X[(size_t)c * NPOS + pos0 + p];
    }
    __syncthreads();
    // LN: 8 warps x 8 rows, fp32 in -> half out
    {
        const float g0 = lng[lane], g1 = lng[lane + 32], g2 = lng[lane + 64], g3 = lng[lane + 96];
        const float bb0 = lnb[lane], bb1 = lnb[lane + 32], bb2 = lnb[lane + 64], bb3 = lnb[lane + 96];
        #pragma unroll 1
        for (int rr = 0; rr < 8; rr++) {
            const int r = warp * 8 + rr;
            const float* row = sXf + r * 132;
            float v0 = row[lane], v1 = row[lane + 32], v2 = row[lane + 64], v3 = row[lane + 96];
            float sm = (v0 + v1) + (v2 + v3);
            float sq = fmaf(v0, v0, fmaf(v1, v1, fmaf(v2, v2, v3 * v3)));
            #pragma unroll
            for (int o = 16; o > 0; o >>= 1) {
                sm += __shfl_xor_sync(0xffffffffu, sm, o);
                sq += __shfl_xor_sync(0xffffffffu, sq, o);
            }
            const float mean = sm * 0.0078125f;
            const float var  = fmaf(-mean, mean, sq * 0.0078125f);
            const float rs   = rsqrtf(var + 1e-5f);
            sX[r * SZS + lane]      = __float2half_rn(fmaf((v0 - mean) * rs, g0, bb0));
            sX[r * SZS + lane + 32] = __float2half_rn(fmaf((v1 - mean) * rs, g1, bb1));
            sX[r * SZS + lane + 64] = __float2half_rn(fmaf((v2 - mean) * rs, g2, bb2));
            sX[r * SZS + lane + 96] = __float2half_rn(fmaf((v3 - mean) * rs, g3, bb3));
        }
    }
    // load w_z [n][k]
    {
        const uint4* src = (const uint4*)(d_Wt + 5 * 16384);
        #pragma unroll
        for (int l = 0; l < 8; l++) {
            const int idx = t + l * 256;
            const int n = idx >> 4, k8 = (idx & 15) * 8;
            *(uint4*)&sW[n * SZS + k8] = src[idx];
        }
    }
    __syncthreads();

    const int aRow = (lane & 7) + ((lane >> 3) & 1) * 8;
    const int aCol = (lane >> 4) * 8;
    const int bRow = (lane & 7) + ((lane >> 4) & 1) * 8;
    const int bCol = ((lane >> 3) & 1) * 8;

    float acc[2][4][4] = {};
    #pragma unroll
    for (int k0 = 0; k0 < 128; k0 += 16) {
        unsigned af[2][4], bf[2][4];
        #pragma unroll
        for (int mt = 0; mt < 2; mt++)
            ldsm4(af[mt], sX + (wy * 32 + mt * 16 + aRow) * SZS + k0 + aCol);
        #pragma unroll
        for (int p = 0; p < 2; p++)
            ldsm4(bf[p], sW + (lw * 32 + p * 16 + bRow) * SZS + k0 + bCol);
        #pragma unroll
        for (int mt = 0; mt < 2; mt++)
            #pragma unroll
            for (int nt = 0; nt < 4; nt++)
                mma16(acc[mt][nt], af[mt], &bf[nt >> 1][(nt & 1) * 2]);
    }

    #pragma unroll
    for (int mt = 0; mt < 2; mt++)
        #pragma unroll
        for (int nt = 0; nt < 4; nt++) {
            const int r = wy * 32 + mt * 16 + (lane >> 2);
            const int c0 = lw * 32 + nt * 8 + (lane & 3) * 2;
            const float bz0 = b_z[c0], bz1 = b_z[c0 + 1];
            const size_t p0 = (size_t)(pos0 + r) * 128 + c0;
            const size_t p1 = (size_t)(pos0 + r + 8) * 128 + c0;
            const float2 g0 = *(const float2*)&d_G[p0];
            const float2 g1 = *(const float2*)&d_G[p1];
            *(float2*)&out[p0] = make_float2((acc[mt][nt][0] + bz0) * g0.x,
                                             (acc[mt][nt][1] + bz1) * g0.y);
            *(float2*)&out[p1] = make_float2((acc[mt][nt][2] + bz0) * g1.x,
                                             (acc[mt][nt][3] + bz1) * g1.y);
        }
}

extern "C" void kernel_launch(void* const* d_in, const int* in_sizes, int n_in,
                              void* d_out, int out_size)
{
    const float* z        = (const float*)d_in[0];
    const float* mask     = (const float*)d_in[1];
    const float* w_ag     = (const float*)d_in[2];
    const float* b_ag     = (const float*)d_in[3];
    const float* w_ap     = (const float*)d_in[4];
    const float* b_ap     = (const float*)d_in[5];
    const float* w_bg     = (const float*)d_in[6];
    const float* b_bg     = (const float*)d_in[7];
    const float* w_bp     = (const float*)d_in[8];
    const float* b_bp     = (const float*)d_in[9];
    const float* w_g      = (const float*)d_in[10];
    const float* b_g      = (const float*)d_in[11];
    const float* w_z      = (const float*)d_in[12];
    const float* b_z      = (const float*)d_in[13];
    const float* ln_in_g  = (const float*)d_in[14];
    const float* ln_in_b  = (const float*)d_in[15];
    const float* ln_out_g = (const float*)d_in[16];
    const float* ln_out_b = (const float*)d_in[17];

    const int KP_SMEM = 2 * 128 * SZS * 2;                       // 69632
    const int KF_SMEM = 64 * 132 * 4 + 64 * SZS * 2 + 128 * SZS * 2;  // 86016
    cudaFuncSetAttribute(kP, cudaFuncAttributeMaxDynamicSharedMemorySize, KP_SMEM);
    cudaFuncSetAttribute(kF, cudaFuncAttributeMaxDynamicSharedMemorySize, KF_SMEM);

    kW<<<6, 256>>>(w_ag, w_ap, w_bg, w_bp, w_g, w_z);
    kP<<<2048, 512, KP_SMEM>>>(z, mask, b_ag, b_ap, b_bg, b_bp, b_g, ln_in_g, ln_in_b);
    kE<<<dim3(4, 4, 128), 256>>>();
    kF<<<4096, 256, KF_SMEM>>>(ln_out_g, ln_out_b, b_z, (float*)d_out);
}

// round 4
// speedup vs baseline: 4.5396x; 1.0735x over previous
#include <cuda_runtime.h>
#include <cuda_fp16.h>
#include <cstdint>

// TriangleMultiplicativeUpdate (outgoing), B=1, N=512, C=128. fp16 mma m16n8k16.
// kW: weights -> [n][k] half.  kP: LN + 5 projections -> half planes + half G.
// kE: 128 per-channel GEMMs, cp.async double-buffered, half X planes out.
// kF: gather X, LN (in-place half smem), @w_z + b_z, * g -> fp32 out.

#define NPOS 262144
#define SZS  136          // smem row stride in halfs (kP/kF)
#define KES  72           // smem row stride in halfs (kE), 144B
#define KEB  9216         // halfs per kE stage buffer (128*KES)

__device__ __half d_Wt[6 * 16384];           // [w][n][k]
__device__ __half d_Ah[(size_t)128 * NPOS];  // 64 MB  [c][i*512+k]
__device__ __half d_Bh[(size_t)128 * NPOS];  // 64 MB
__device__ __half d_Xh[(size_t)128 * NPOS];  // 64 MB  [c][i*512+j]
__device__ __half d_Gh[(size_t)NPOS * 128];  // 64 MB  [pos][c]

__device__ __forceinline__ float sigf(float x) { return 1.0f / (1.0f + __expf(-x)); }

__device__ __forceinline__ void mma16(float* d, const unsigned* a, const unsigned* b) {
    asm volatile(
        "mma.sync.aligned.m16n8k16.row.col.f32.f16.f16.f32 "
        "{%0,%1,%2,%3}, {%4,%5,%6,%7}, {%8,%9}, {%0,%1,%2,%3};\n"
        : "+f"(d[0]), "+f"(d[1]), "+f"(d[2]), "+f"(d[3])
        : "r"(a[0]), "r"(a[1]), "r"(a[2]), "r"(a[3]), "r"(b[0]), "r"(b[1]));
}

__device__ __forceinline__ void ldsm4(unsigned* r, const __half* p) {
    unsigned addr = (unsigned)__cvta_generic_to_shared(p);
    asm volatile("ldmatrix.sync.aligned.m8n8.x4.shared.b16 {%0,%1,%2,%3}, [%4];"
                 : "=r"(r[0]), "=r"(r[1]), "=r"(r[2]), "=r"(r[3]) : "r"(addr));
}

__device__ __forceinline__ void cp16(void* s, const void* g) {
    unsigned sa = (unsigned)__cvta_generic_to_shared(s);
    asm volatile("cp.async.cg.shared.global [%0], [%1], 16;" :: "r"(sa), "l"(g));
}

// ---------------- kW: weight transpose+convert ------------------------------
__global__ __launch_bounds__(256) void kW(
    const float* __restrict__ w_ag, const float* __restrict__ w_ap,
    const float* __restrict__ w_bg, const float* __restrict__ w_bp,
    const float* __restrict__ w_g,  const float* __restrict__ w_z)
{
    __shared__ float s[128 * 132];
    const float* srcs[6] = {w_ag, w_ap, w_bg, w_bp, w_g, w_z};
    const float* w = srcs[blockIdx.x];
    const int t = threadIdx.x;
    #pragma unroll
    for (int l = 0; l < 64; l++) {
        const int idx = t + l * 256;
        s[(idx >> 7) * 132 + (idx & 127)] = w[idx];   // [k][n]
    }
    __syncthreads();
    __half* dst = d_Wt + blockIdx.x * 16384;
    #pragma unroll
    for (int l = 0; l < 64; l++) {
        const int idx = t + l * 256;                  // idx = n*128 + k
        dst[idx] = __float2half_rn(s[(idx & 127) * 132 + (idx >> 7)]);
    }
}

// ---------------- kP ---------------------------------------------------------
__device__ __forceinline__ void gemmP(
    const __half* __restrict__ wt, __half* sW, const __half* sZ,
    float acc[2][4][4], int t, int wy, int lw,
    int aRow, int aCol, int bRow, int bCol)
{
    __syncthreads();
    const uint4* src = (const uint4*)wt;
    #pragma unroll
    for (int l = 0; l < 4; l++) {
        const int idx = t + l * 512;                 // 2048 uint4
        const int n = idx >> 4, k8 = (idx & 15) * 8;
        *(uint4*)&sW[n * SZS + k8] = src[idx];
    }
    __syncthreads();
    #pragma unroll
    for (int k0 = 0; k0 < 128; k0 += 16) {
        unsigned af[2][4], bf[2][4];
        #pragma unroll
        for (int mt = 0; mt < 2; mt++)
            ldsm4(af[mt], sZ + (wy * 32 + mt * 16 + aRow) * SZS + k0 + aCol);
        #pragma unroll
        for (int p = 0; p < 2; p++)
            ldsm4(bf[p], sW + (lw * 32 + p * 16 + bRow) * SZS + k0 + bCol);
        #pragma unroll
        for (int mt = 0; mt < 2; mt++)
            #pragma unroll
            for (int nt = 0; nt < 4; nt++)
                mma16(acc[mt][nt], af[mt], &bf[nt >> 1][(nt & 1) * 2]);
    }
}

__global__ __launch_bounds__(512) void kP(
    const float* __restrict__ z,    const float* __restrict__ mask,
    const float* __restrict__ b_ag, const float* __restrict__ b_ap,
    const float* __restrict__ b_bg, const float* __restrict__ b_bp,
    const float* __restrict__ b_g,
    const float* __restrict__ lng,  const float* __restrict__ lnb)
{
    extern __shared__ __half sh[];
    __half* sZ = sh;                 // [128][SZS]
    __half* sW = sh + 128 * SZS;     // [128][SZS]
    const int t = threadIdx.x, lane = t & 31, warp = t >> 5;
    const int wy = warp >> 2, lw = warp & 3;
    const int pos0 = blockIdx.x * 128;

    {
        const float g0 = lng[lane], g1 = lng[lane + 32], g2 = lng[lane + 64], g3 = lng[lane + 96];
        const float bb0 = lnb[lane], bb1 = lnb[lane + 32], bb2 = lnb[lane + 64], bb3 = lnb[lane + 96];
        #pragma unroll 1
        for (int rr = 0; rr < 8; rr++) {
            const int r = warp * 8 + rr;
            const float* zr = z + (size_t)(pos0 + r) * 128;
            float v0 = zr[lane], v1 = zr[lane + 32], v2 = zr[lane + 64], v3 = zr[lane + 96];
            float sm = (v0 + v1) + (v2 + v3);
            float sq = fmaf(v0, v0, fmaf(v1, v1, fmaf(v2, v2, v3 * v3)));
            #pragma unroll
            for (int o = 16; o > 0; o >>= 1) {
                sm += __shfl_xor_sync(0xffffffffu, sm, o);
                sq += __shfl_xor_sync(0xffffffffu, sq, o);
            }
            const float mean = sm * 0.0078125f;
            const float var  = fmaf(-mean, mean, sq * 0.0078125f);
            const float rs   = rsqrtf(var + 1e-5f);
            sZ[r * SZS + lane]      = __float2half_rn(fmaf((v0 - mean) * rs, g0, bb0));
            sZ[r * SZS + lane + 32] = __float2half_rn(fmaf((v1 - mean) * rs, g1, bb1));
            sZ[r * SZS + lane + 64] = __float2half_rn(fmaf((v2 - mean) * rs, g2, bb2));
            sZ[r * SZS + lane + 96] = __float2half_rn(fmaf((v3 - mean) * rs, g3, bb3));
        }
    }

    const int aRow = (lane & 7) + ((lane >> 3) & 1) * 8;
    const int aCol = (lane >> 4) * 8;
    const int bRow = (lane & 7) + ((lane >> 4) & 1) * 8;
    const int bCol = ((lane >> 3) & 1) * 8;
    const int rB = wy * 32 + (lane >> 2);
    const int cB = lw * 32 + (lane & 3) * 2;

    #pragma unroll 1
    for (int pair = 0; pair < 2; pair++) {
        const float* biasG = pair ? b_bg : b_ag;
        const float* biasP = pair ? b_bp : b_ap;
        __half* plane = pair ? d_Bh : d_Ah;

        float accg[2][4][4] = {};
        gemmP(d_Wt + (pair * 2 + 0) * 16384, sW, sZ, accg, t, wy, lw, aRow, aCol, bRow, bCol);
        float gate[2][4][4];
        #pragma unroll
        for (int mt = 0; mt < 2; mt++)
            #pragma unroll
            for (int nt = 0; nt < 4; nt++) {
                const int c = cB + nt * 8;
                const float bg0 = biasG[c], bg1 = biasG[c + 1];
                gate[mt][nt][0] = sigf(accg[mt][nt][0] + bg0);
                gate[mt][nt][1] = sigf(accg[mt][nt][1] + bg1);
                gate[mt][nt][2] = sigf(accg[mt][nt][2] + bg0);
                gate[mt][nt][3] = sigf(accg[mt][nt][3] + bg1);
            }
        float accp[2][4][4] = {};
        gemmP(d_Wt + (pair * 2 + 1) * 16384, sW, sZ, accp, t, wy, lw, aRow, aCol, bRow, bCol);
        __syncthreads();
        #pragma unroll
        for (int mt = 0; mt < 2; mt++) {
            const int r = rB + mt * 16;
            const float m0 = mask[pos0 + r], m1 = mask[pos0 + r + 8];
            #pragma unroll
            for (int nt = 0; nt < 4; nt++) {
                const int c = cB + nt * 8;
                const float bp0 = biasP[c], bp1 = biasP[c + 1];
                *(__half2*)&sW[r * SZS + c] = __floats2half2_rn(
                    m0 * gate[mt][nt][0] * (accp[mt][nt][0] + bp0),
                    m0 * gate[mt][nt][1] * (accp[mt][nt][1] + bp1));
                *(__half2*)&sW[(r + 8) * SZS + c] = __floats2half2_rn(
                    m1 * gate[mt][nt][2] * (accp[mt][nt][2] + bp0),
                    m1 * gate[mt][nt][3] * (accp[mt][nt][3] + bp1));
            }
        }
        __syncthreads();
        #pragma unroll
        for (int l = 0; l < 32; l++) {
            const int idx = t + l * 512;
            const int c = idx >> 7, p = idx & 127;
            plane[(size_t)c * NPOS + pos0 + p] = sW[p * SZS + c];
        }
    }

    {
        float accq[2][4][4] = {};
        gemmP(d_Wt + 4 * 16384, sW, sZ, accq, t, wy, lw, aRow, aCol, bRow, bCol);
        #pragma unroll
        for (int mt = 0; mt < 2; mt++) {
            const int r = rB + mt * 16;
            #pragma unroll
            for (int nt = 0; nt < 4; nt++) {
                const int c = cB + nt * 8;
                const float bg0 = b_g[c], bg1 = b_g[c + 1];
                *(__half2*)&d_Gh[(size_t)(pos0 + r) * 128 + c] =
                    __floats2half2_rn(sigf(accq[mt][nt][0] + bg0), sigf(accq[mt][nt][1] + bg1));
                *(__half2*)&d_Gh[(size_t)(pos0 + r + 8) * 128 + c] =
                    __floats2half2_rn(sigf(accq[mt][nt][2] + bg0), sigf(accq[mt][nt][3] + bg1));
            }
        }
    }
}

// ---------------- kE: per-channel GEMM, cp.async double-buffered ------------
__global__ __launch_bounds__(256) void kE()
{
    extern __shared__ __half she[];
    __half* sA = she;                 // [2][KEB]
    __half* sB = she + 2 * KEB;       // [2][KEB]
    const int t = threadIdx.x, lane = t & 31, warp = t >> 5;
    const int wy = warp >> 2, lw = warp & 3;
    const int j0 = blockIdx.x * 128, i0 = blockIdx.y * 128, ch = blockIdx.z;
    const __half* __restrict__ Ap = d_Ah + (size_t)ch * NPOS;
    const __half* __restrict__ Bp = d_Bh + (size_t)ch * NPOS;

    const int aRow = (lane & 7) + ((lane >> 3) & 1) * 8;
    const int aCol = (lane >> 4) * 8;
    const int bRow = (lane & 7) + ((lane >> 4) & 1) * 8;
    const int bCol = ((lane >> 3) & 1) * 8;

    const int lr = t >> 3, lk8 = (t & 7) * 8;    // 32 rows x 8 chunks per 256 threads

    float acc[4][4][4] = {};

    // prologue: stage 0
    #pragma unroll
    for (int l = 0; l < 4; l++) {
        const int r = lr + l * 32;
        cp16(&sA[r * KES + lk8], &Ap[(size_t)(i0 + r) * 512 + lk8]);
        cp16(&sB[r * KES + lk8], &Bp[(size_t)(j0 + r) * 512 + lk8]);
    }
    asm volatile("cp.async.commit_group;");

    #pragma unroll 1
    for (int s = 0; s < 8; s++) {
        if (s < 7) {
            const int buf = (s + 1) & 1;
            const int kt = (s + 1) * 64;
            #pragma unroll
            for (int l = 0; l < 4; l++) {
                const int r = lr + l * 32;
                cp16(&sA[buf * KEB + r * KES + lk8], &Ap[(size_t)(i0 + r) * 512 + kt + lk8]);
                cp16(&sB[buf * KEB + r * KES + lk8], &Bp[(size_t)(j0 + r) * 512 + kt + lk8]);
            }
            asm volatile("cp.async.commit_group;");
            asm volatile("cp.async.wait_group 1;");
        } else {
            asm volatile("cp.async.wait_group 0;");
        }
        __syncthreads();
        const __half* bA = sA + (s & 1) * KEB;
        const __half* bB = sB + (s & 1) * KEB;
        #pragma unroll
        for (int kk = 0; kk < 64; kk += 16) {
            unsigned af[4][4], bf[2][4];
            #pragma unroll
            for (int mt = 0; mt < 4; mt++)
                ldsm4(af[mt], bA + (wy * 64 + mt * 16 + aRow) * KES + kk + aCol);
            #pragma unroll
            for (int p = 0; p < 2; p++)
                ldsm4(bf[p], bB + (lw * 32 + p * 16 + bRow) * KES + kk + bCol);
            #pragma unroll
            for (int mt = 0; mt < 4; mt++)
                #pragma unroll
                for (int nt = 0; nt < 4; nt++)
                    mma16(acc[mt][nt], af[mt], &bf[nt >> 1][(nt & 1) * 2]);
        }
        __syncthreads();
    }

    // stage output through smem (reuse sA region: 128 x 136 halfs = 34.8KB < 36KB)
    __half* sSt = sA;
    #pragma unroll
    for (int mt = 0; mt < 4; mt++)
        #pragma unroll
        for (int nt = 0; nt < 4; nt++) {
            const int r = wy * 64 + mt * 16 + (lane >> 2);
            const int c = lw * 32 + nt * 8 + (lane & 3) * 2;
            *(__half2*)&sSt[r * 136 + c]       = __floats2half2_rn(acc[mt][nt][0], acc[mt][nt][1]);
            *(__half2*)&sSt[(r + 8) * 136 + c] = __floats2half2_rn(acc[mt][nt][2], acc[mt][nt][3]);
        }
    __syncthreads();
    __half* Xp = d_Xh + (size_t)ch * NPOS;
    #pragma unroll
    for (int l = 0; l < 8; l++) {
        const int idx = t + l * 256;           // 2048 16B chunks
        const int r = idx >> 4, c16 = idx & 15;
        *(uint4*)&Xp[(size_t)(i0 + r) * 512 + j0 + c16 * 8] = *(const uint4*)&sSt[r * 136 + c16 * 8];
    }
}

// ---------------- kF: LN(X) @ w_z + b_z, * g ---------------------------------
__global__ __launch_bounds__(256) void kF(
    const float* __restrict__ lng, const float* __restrict__ lnb,
    const float* __restrict__ b_z, float* __restrict__ out)
{
    extern __shared__ __half shf[];
    __half* sX = shf;                 // [64][SZS], in-place LN
    __half* sW = shf + 64 * SZS;      // [128][SZS]
    const int t = threadIdx.x, lane = t & 31, warp = t >> 5;
    const int wy = warp >> 2, lw = warp & 3;
    const int pos0 = blockIdx.x * 64;

    // gather X planes (half2 along pos) -> row-major [p][c]
    #pragma unroll
    for (int l = 0; l < 16; l++) {
        const int idx = t + l * 256;          // 4096 = 128c x 32 p-pairs
        const int c = idx >> 5, p2 = idx & 31;
        const __half2 v = *(const __half2*)&d_Xh[(size_t)c * NPOS + pos0 + 2 * p2];
        sX[(2 * p2) * SZS + c]     = v.x;
        sX[(2 * p2 + 1) * SZS + c] = v.y;
    }
    // load w_z [n][k] while gather lands
    {
        const uint4* src = (const uint4*)(d_Wt + 5 * 16384);
        #pragma unroll
        for (int l = 0; l < 8; l++) {
            const int idx = t + l * 256;
            const int n = idx >> 4, k8 = (idx & 15) * 8;
            *(uint4*)&sW[n * SZS + k8] = src[idx];
        }
    }
    __syncthreads();
    // LN in place: 8 warps x 8 rows
    {
        const float g0 = lng[lane], g1 = lng[lane + 32], g2 = lng[lane + 64], g3 = lng[lane + 96];
        const float bb0 = lnb[lane], bb1 = lnb[lane + 32], bb2 = lnb[lane + 64], bb3 = lnb[lane + 96];
        #pragma unroll 1
        for (int rr = 0; rr < 8; rr++) {
            const int r = warp * 8 + rr;
            __half* row = sX + r * SZS;
            float v0 = __half2float(row[lane]),      v1 = __half2float(row[lane + 32]);
            float v2 = __half2float(row[lane + 64]), v3 = __half2float(row[lane + 96]);
            float sm = (v0 + v1) + (v2 + v3);
            float sq = fmaf(v0, v0, fmaf(v1, v1, fmaf(v2, v2, v3 * v3)));
            #pragma unroll
            for (int o = 16; o > 0; o >>= 1) {
                sm += __shfl_xor_sync(0xffffffffu, sm, o);
                sq += __shfl_xor_sync(0xffffffffu, sq, o);
            }
            const float mean = sm * 0.0078125f;
            const float var  = fmaf(-mean, mean, sq * 0.0078125f);
            const float rs   = rsqrtf(var + 1e-5f);
            row[lane]      = __float2half_rn(fmaf((v0 - mean) * rs, g0, bb0));
            row[lane + 32] = __float2half_rn(fmaf((v1 - mean) * rs, g1, bb1));
            row[lane + 64] = __float2half_rn(fmaf((v2 - mean) * rs, g2, bb2));
            row[lane + 96] = __float2half_rn(fmaf((v3 - mean) * rs, g3, bb3));
        }
    }
    __syncthreads();

    const int aRow = (lane & 7) + ((lane >> 3) & 1) * 8;
    const int aCol = (lane >> 4) * 8;
    const int bRow = (lane & 7) + ((lane >> 4) & 1) * 8;
    const int bCol = ((lane >> 3) & 1) * 8;

    float acc[2][4][4] = {};
    #pragma unroll
    for (int k0 = 0; k0 < 128; k0 += 16) {
        unsigned af[2][4], bf[2][4];
        #pragma unroll
        for (int mt = 0; mt < 2; mt++)
            ldsm4(af[mt], sX + (wy * 32 + mt * 16 + aRow) * SZS + k0 + aCol);
        #pragma unroll
        for (int p = 0; p < 2; p++)
            ldsm4(bf[p], sW + (lw * 32 + p * 16 + bRow) * SZS + k0 + bCol);
        #pragma unroll
        for (int mt = 0; mt < 2; mt++)
            #pragma unroll
            for (int nt = 0; nt < 4; nt++)
                mma16(acc[mt][nt], af[mt], &bf[nt >> 1][(nt & 1) * 2]);
    }

    #pragma unroll
    for (int mt = 0; mt < 2; mt++)
        #pragma unroll
        for (int nt = 0; nt < 4; nt++) {
            const int r = wy * 32 + mt * 16 + (lane >> 2);
            const int c0 = lw * 32 + nt * 8 + (lane & 3) * 2;
            const float bz0 = b_z[c0], bz1 = b_z[c0 + 1];
            const size_t p0 = (size_t)(pos0 + r) * 128 + c0;
            const size_t p1 = (size_t)(pos0 + r + 8) * 128 + c0;
            const float2 g0 = __half22float2(*(const __half2*)&d_Gh[p0]);
            const float2 g1 = __half22float2(*(const __half2*)&d_Gh[p1]);
            *(float2*)&out[p0] = make_float2((acc[mt][nt][0] + bz0) * g0.x,
                                             (acc[mt][nt][1] + bz1) * g0.y);
            *(float2*)&out[p1] = make_float2((acc[mt][nt][2] + bz0) * g1.x,
                                             (acc[mt][nt][3] + bz1) * g1.y);
        }
}

extern "C" void kernel_launch(void* const* d_in, const int* in_sizes, int n_in,
                              void* d_out, int out_size)
{
    const float* z        = (const float*)d_in[0];
    const float* mask     = (const float*)d_in[1];
    const float* w_ag     = (const float*)d_in[2];
    const float* b_ag     = (const float*)d_in[3];
    const float* w_ap     = (const float*)d_in[4];
    const float* b_ap     = (const float*)d_in[5];
    const float* w_bg     = (const float*)d_in[6];
    const float* b_bg     = (const float*)d_in[7];
    const float* w_bp     = (const float*)d_in[8];
    const float* b_bp     = (const float*)d_in[9];
    const float* w_g      = (const float*)d_in[10];
    const float* b_g      = (const float*)d_in[11];
    const float* w_z      = (const float*)d_in[12];
    const float* b_z      = (const float*)d_in[13];
    const float* ln_in_g  = (const float*)d_in[14];
    const float* ln_in_b  = (const float*)d_in[15];
    const float* ln_out_g = (const float*)d_in[16];
    const float* ln_out_b = (const float*)d_in[17];

    const int KP_SMEM = 2 * 128 * SZS * 2;            // 69632
    const int KE_SMEM = 4 * KEB * 2;                  // 73728
    const int KF_SMEM = (64 + 128) * SZS * 2;         // 52224
    cudaFuncSetAttribute(kP, cudaFuncAttributeMaxDynamicSharedMemorySize, KP_SMEM);
    cudaFuncSetAttribute(kE, cudaFuncAttributeMaxDynamicSharedMemorySize, KE_SMEM);
    cudaFuncSetAttribute(kF, cudaFuncAttributeMaxDynamicSharedMemorySize, KF_SMEM);

    kW<<<6, 256>>>(w_ag, w_ap, w_bg, w_bp, w_g, w_z);
    kP<<<2048, 512, KP_SMEM>>>(z, mask, b_ag, b_ap, b_bg, b_bp, b_g, ln_in_g, ln_in_b);
    kE<<<dim3(4, 4, 128), 256, KE_SMEM>>>();
    kF<<<4096, 256, KF_SMEM>>>(ln_out_g, ln_out_b, b_z, (float*)d_out);
}

// round 5
// speedup vs baseline: 4.6905x; 1.0332x over previous
#include <cuda_runtime.h>
#include <cuda_fp16.h>
#include <cstdint>

// TriangleMultiplicativeUpdate (outgoing), B=1, N=512, C=128. fp16 mma m16n8k16.
// kW: weights -> [n][k] half.
// kP: LN + 5 projections, cp.async double-buffered weights -> half planes + half G.
// kE: 128 per-channel GEMMs, cp.async double-buffered, half X planes out.
// kF: stmatrix-trans gather of X, LN, @w_z + b_z, * g -> fp32 out.

#define NPOS 262144
#define SZS  136          // smem row stride in halfs (kP/kF)
#define KES  72           // smem row stride in halfs (kE)
#define KEB  9216         // halfs per kE stage buffer (128*KES)

__device__ __half d_Wt[6 * 16384];           // [w][n][k]
__device__ __half d_Ah[(size_t)128 * NPOS];  // 64 MB  [c][i*512+k]
__device__ __half d_Bh[(size_t)128 * NPOS];  // 64 MB
__device__ __half d_Xh[(size_t)128 * NPOS];  // 64 MB  [c][i*512+j]
__device__ __half d_Gh[(size_t)NPOS * 128];  // 64 MB  [pos][c]

__device__ __forceinline__ float sigf(float x) { return 1.0f / (1.0f + __expf(-x)); }

__device__ __forceinline__ void mma16(float* d, const unsigned* a, const unsigned* b) {
    asm volatile(
        "mma.sync.aligned.m16n8k16.row.col.f32.f16.f16.f32 "
        "{%0,%1,%2,%3}, {%4,%5,%6,%7}, {%8,%9}, {%0,%1,%2,%3};\n"
        : "+f"(d[0]), "+f"(d[1]), "+f"(d[2]), "+f"(d[3])
        : "r"(a[0]), "r"(a[1]), "r"(a[2]), "r"(a[3]), "r"(b[0]), "r"(b[1]));
}

__device__ __forceinline__ void ldsm4(unsigned* r, const __half* p) {
    unsigned addr = (unsigned)__cvta_generic_to_shared(p);
    asm volatile("ldmatrix.sync.aligned.m8n8.x4.shared.b16 {%0,%1,%2,%3}, [%4];"
                 : "=r"(r[0]), "=r"(r[1]), "=r"(r[2]), "=r"(r[3]) : "r"(addr));
}

__device__ __forceinline__ void stsm4t(__half* p, unsigned r0, unsigned r1,
                                       unsigned r2, unsigned r3) {
    unsigned addr = (unsigned)__cvta_generic_to_shared(p);
    asm volatile("stmatrix.sync.aligned.m8n8.x4.trans.shared.b16 [%0], {%1,%2,%3,%4};"
                 :: "r"(addr), "r"(r0), "r"(r1), "r"(r2), "r"(r3) : "memory");
}

__device__ __forceinline__ void cp16(void* s, const void* g) {
    unsigned sa = (unsigned)__cvta_generic_to_shared(s);
    asm volatile("cp.async.cg.shared.global [%0], [%1], 16;" :: "r"(sa), "l"(g));
}
#define CPCOMMIT() asm volatile("cp.async.commit_group;")
#define CPWAIT(n)  asm volatile("cp.async.wait_group %0;" :: "n"(n))

// ---------------- kW: weight transpose+convert ------------------------------
__global__ __launch_bounds__(256) void kW(
    const float* __restrict__ w_ag, const float* __restrict__ w_ap,
    const float* __restrict__ w_bg, const float* __restrict__ w_bp,
    const float* __restrict__ w_g,  const float* __restrict__ w_z)
{
    __shared__ float s[128 * 132];
    const float* srcs[6] = {w_ag, w_ap, w_bg, w_bp, w_g, w_z};
    const float* w = srcs[blockIdx.x];
    const int t = threadIdx.x;
    #pragma unroll
    for (int l = 0; l < 64; l++) {
        const int idx = t + l * 256;
        s[(idx >> 7) * 132 + (idx & 127)] = w[idx];   // [k][n]
    }
    __syncthreads();
    __half* dst = d_Wt + blockIdx.x * 16384;
    #pragma unroll
    for (int l = 0; l < 64; l++) {
        const int idx = t + l * 256;                  // idx = n*128 + k
        dst[idx] = __float2half_rn(s[(idx & 127) * 132 + (idx >> 7)]);
    }
}

// ---------------- kP ---------------------------------------------------------
__device__ __forceinline__ void prefW(__half* buf, const __half* __restrict__ wt, int t) {
    #pragma unroll
    for (int l = 0; l < 4; l++) {
        const int idx = t + l * 512;                 // 2048 uint4
        const int n = idx >> 4, k8 = (idx & 15) * 8;
        cp16(&buf[n * SZS + k8], &wt[n * 128 + k8]);
    }
    CPCOMMIT();
}

__device__ __forceinline__ void gemmC(
    const __half* sW, const __half* sZ, float acc[2][4][4],
    int wy, int lw, int aRow, int aCol, int bRow, int bCol)
{
    #pragma unroll
    for (int k0 = 0; k0 < 128; k0 += 16) {
        unsigned af[2][4], bf[2][4];
        #pragma unroll
        for (int mt = 0; mt < 2; mt++)
            ldsm4(af[mt], sZ + (wy * 32 + mt * 16 + aRow) * SZS + k0 + aCol);
        #pragma unroll
        for (int p = 0; p < 2; p++)
            ldsm4(bf[p], sW + (lw * 32 + p * 16 + bRow) * SZS + k0 + bCol);
        #pragma unroll
        for (int mt = 0; mt < 2; mt++)
            #pragma unroll
            for (int nt = 0; nt < 4; nt++)
                mma16(acc[mt][nt], af[mt], &bf[nt >> 1][(nt & 1) * 2]);
    }
}

__global__ __launch_bounds__(512) void kP(
    const float* __restrict__ z,    const float* __restrict__ mask,
    const float* __restrict__ b_ag, const float* __restrict__ b_ap,
    const float* __restrict__ b_bg, const float* __restrict__ b_bp,
    const float* __restrict__ b_g,
    const float* __restrict__ lng,  const float* __restrict__ lnb)
{
    extern __shared__ __half sh[];
    __half* sZ  = sh;                  // [128][SZS]
    __half* sW0 = sh + 128 * SZS;      // [128][SZS]
    __half* sW1 = sh + 2 * 128 * SZS;  // [128][SZS]
    __half* sSt = sh + 3 * 128 * SZS;  // [128][SZS] staging
    const int t = threadIdx.x, lane = t & 31, warp = t >> 5;
    const int wy = warp >> 2, lw = warp & 3;
    const int pos0 = blockIdx.x * 128;

    prefW(sW0, d_Wt + 0 * 16384, t);   // w_ag in flight during LN

    {
        const float g0 = lng[lane], g1 = lng[lane + 32], g2 = lng[lane + 64], g3 = lng[lane + 96];
        const float bb0 = lnb[lane], bb1 = lnb[lane + 32], bb2 = lnb[lane + 64], bb3 = lnb[lane + 96];
        #pragma unroll 1
        for (int rr = 0; rr < 8; rr++) {
            const int r = warp * 8 + rr;
            const float* zr = z + (size_t)(pos0 + r) * 128;
            float v0 = zr[lane], v1 = zr[lane + 32], v2 = zr[lane + 64], v3 = zr[lane + 96];
            float sm = (v0 + v1) + (v2 + v3);
            float sq = fmaf(v0, v0, fmaf(v1, v1, fmaf(v2, v2, v3 * v3)));
            #pragma unroll
            for (int o = 16; o > 0; o >>= 1) {
                sm += __shfl_xor_sync(0xffffffffu, sm, o);
                sq += __shfl_xor_sync(0xffffffffu, sq, o);
            }
            const float mean = sm * 0.0078125f;
            const float var  = fmaf(-mean, mean, sq * 0.0078125f);
            const float rs   = rsqrtf(var + 1e-5f);
            sZ[r * SZS + lane]      = __float2half_rn(fmaf((v0 - mean) * rs, g0, bb0));
            sZ[r * SZS + lane + 32] = __float2half_rn(fmaf((v1 - mean) * rs, g1, bb1));
            sZ[r * SZS + lane + 64] = __float2half_rn(fmaf((v2 - mean) * rs, g2, bb2));
            sZ[r * SZS + lane + 96] = __float2half_rn(fmaf((v3 - mean) * rs, g3, bb3));
        }
    }
    prefW(sW1, d_Wt + 1 * 16384, t);   // w_ap

    const int aRow = (lane & 7) + ((lane >> 3) & 1) * 8;
    const int aCol = (lane >> 4) * 8;
    const int bRow = (lane & 7) + ((lane >> 4) & 1) * 8;
    const int bCol = ((lane >> 3) & 1) * 8;
    const int rB = wy * 32 + (lane >> 2);
    const int cB = lw * 32 + (lane & 3) * 2;

    #pragma unroll 1
    for (int pair = 0; pair < 2; pair++) {
        const float* biasG = pair ? b_bg : b_ag;
        const float* biasP = pair ? b_bp : b_ap;
        __half* plane = pair ? d_Bh : d_Ah;

        // gate pass (q = 2*pair): buffer sW0
        float accg[2][4][4] = {};
        CPWAIT(1);
        __syncthreads();
        gemmC(sW0, sZ, accg, wy, lw, aRow, aCol, bRow, bCol);
        __syncthreads();
        if (pair == 0) prefW(sW0, d_Wt + 2 * 16384, t);   // w_bg
        else           prefW(sW0, d_Wt + 4 * 16384, t);   // w_g
        // fold sigmoid+bias into accg
        #pragma unroll
        for (int mt = 0; mt < 2; mt++)
            #pragma unroll
            for (int nt = 0; nt < 4; nt++) {
                const int c = cB + nt * 8;
                const float bg0 = biasG[c], bg1 = biasG[c + 1];
                accg[mt][nt][0] = sigf(accg[mt][nt][0] + bg0);
                accg[mt][nt][1] = sigf(accg[mt][nt][1] + bg1);
                accg[mt][nt][2] = sigf(accg[mt][nt][2] + bg0);
                accg[mt][nt][3] = sigf(accg[mt][nt][3] + bg1);
            }

        // proj pass (q = 2*pair+1): buffer sW1
        float accp[2][4][4] = {};
        CPWAIT(1);
        __syncthreads();
        gemmC(sW1, sZ, accp, wy, lw, aRow, aCol, bRow, bCol);
        __syncthreads();
        if (pair == 0) prefW(sW1, d_Wt + 3 * 16384, t);   // w_bp

        // combine + transposed flush via staging
        #pragma unroll
        for (int mt = 0; mt < 2; mt++) {
            const int r = rB + mt * 16;
            const float m0 = mask[pos0 + r], m1 = mask[pos0 + r + 8];
            #pragma unroll
            for (int nt = 0; nt < 4; nt++) {
                const int c = cB + nt * 8;
                const float bp0 = biasP[c], bp1 = biasP[c + 1];
                *(__half2*)&sSt[r * SZS + c] = __floats2half2_rn(
                    m0 * accg[mt][nt][0] * (accp[mt][nt][0] + bp0),
                    m0 * accg[mt][nt][1] * (accp[mt][nt][1] + bp1));
                *(__half2*)&sSt[(r + 8) * SZS + c] = __floats2half2_rn(
                    m1 * accg[mt][nt][2] * (accp[mt][nt][2] + bp0),
                    m1 * accg[mt][nt][3] * (accp[mt][nt][3] + bp1));
            }
        }
        __syncthreads();
        #pragma unroll
        for (int l = 0; l < 32; l++) {
            const int idx = t + l * 512;
            const int c = idx >> 7, p = idx & 127;
            plane[(size_t)c * NPOS + pos0 + p] = sSt[p * SZS + c];
        }
    }

    // g pass (q=4): buffer sW0
    {
        float accq[2][4][4] = {};
        CPWAIT(0);
        __syncthreads();
        gemmC(sW0, sZ, accq, wy, lw, aRow, aCol, bRow, bCol);
        #pragma unroll
        for (int mt = 0; mt < 2; mt++) {
            const int r = rB + mt * 16;
            #pragma unroll
            for (int nt = 0; nt < 4; nt++) {
                const int c = cB + nt * 8;
                const float bg0 = b_g[c], bg1 = b_g[c + 1];
                *(__half2*)&d_Gh[(size_t)(pos0 + r) * 128 + c] =
                    __floats2half2_rn(sigf(accq[mt][nt][0] + bg0), sigf(accq[mt][nt][1] + bg1));
                *(__half2*)&d_Gh[(size_t)(pos0 + r + 8) * 128 + c] =
                    __floats2half2_rn(sigf(accq[mt][nt][2] + bg0), sigf(accq[mt][nt][3] + bg1));
            }
        }
    }
}

// ---------------- kE: per-channel GEMM, cp.async double-buffered ------------
__global__ __launch_bounds__(256) void kE()
{
    extern __shared__ __half she[];
    __half* sA = she;                 // [2][KEB]
    __half* sB = she + 2 * KEB;       // [2][KEB]
    const int t = threadIdx.x, lane = t & 31, warp = t >> 5;
    const int wy = warp >> 2, lw = warp & 3;
    const int j0 = blockIdx.x * 128, i0 = blockIdx.y * 128, ch = blockIdx.z;
    const __half* __restrict__ Ap = d_Ah + (size_t)ch * NPOS;
    const __half* __restrict__ Bp = d_Bh + (size_t)ch * NPOS;

    const int aRow = (lane & 7) + ((lane >> 3) & 1) * 8;
    const int aCol = (lane >> 4) * 8;
    const int bRow = (lane & 7) + ((lane >> 4) & 1) * 8;
    const int bCol = ((lane >> 3) & 1) * 8;

    const int lr = t >> 3, lk8 = (t & 7) * 8;

    float acc[4][4][4] = {};

    #pragma unroll
    for (int l = 0; l < 4; l++) {
        const int r = lr + l * 32;
        cp16(&sA[r * KES + lk8], &Ap[(size_t)(i0 + r) * 512 + lk8]);
        cp16(&sB[r * KES + lk8], &Bp[(size_t)(j0 + r) * 512 + lk8]);
    }
    CPCOMMIT();

    #pragma unroll 1
    for (int s = 0; s < 8; s++) {
        if (s < 7) {
            const int buf = (s + 1) & 1;
            const int kt = (s + 1) * 64;
            #pragma unroll
            for (int l = 0; l < 4; l++) {
                const int r = lr + l * 32;
                cp16(&sA[buf * KEB + r * KES + lk8], &Ap[(size_t)(i0 + r) * 512 + kt + lk8]);
                cp16(&sB[buf * KEB + r * KES + lk8], &Bp[(size_t)(j0 + r) * 512 + kt + lk8]);
            }
            CPCOMMIT();
            CPWAIT(1);
        } else {
            CPWAIT(0);
        }
        __syncthreads();
        const __half* bA = sA + (s & 1) * KEB;
        const __half* bB = sB + (s & 1) * KEB;
        #pragma unroll
        for (int kk = 0; kk < 64; kk += 16) {
            unsigned af[4][4], bf[2][4];
            #pragma unroll
            for (int mt = 0; mt < 4; mt++)
                ldsm4(af[mt], bA + (wy * 64 + mt * 16 + aRow) * KES + kk + aCol);
            #pragma unroll
            for (int p = 0; p < 2; p++)
                ldsm4(bf[p], bB + (lw * 32 + p * 16 + bRow) * KES + kk + bCol);
            #pragma unroll
            for (int mt = 0; mt < 4; mt++)
                #pragma unroll
                for (int nt = 0; nt < 4; nt++)
                    mma16(acc[mt][nt], af[mt], &bf[nt >> 1][(nt & 1) * 2]);
        }
        __syncthreads();
    }

    __half* sSt = sA;   // reuse: 128 x 136 halfs
    #pragma unroll
    for (int mt = 0; mt < 4; mt++)
        #pragma unroll
        for (int nt = 0; nt < 4; nt++) {
            const int r = wy * 64 + mt * 16 + (lane >> 2);
            const int c = lw * 32 + nt * 8 + (lane & 3) * 2;
            *(__half2*)&sSt[r * 136 + c]       = __floats2half2_rn(acc[mt][nt][0], acc[mt][nt][1]);
            *(__half2*)&sSt[(r + 8) * 136 + c] = __floats2half2_rn(acc[mt][nt][2], acc[mt][nt][3]);
        }
    __syncthreads();
    __half* Xp = d_Xh + (size_t)ch * NPOS;
    #pragma unroll
    for (int l = 0; l < 8; l++) {
        const int idx = t + l * 256;
        const int r = idx >> 4, c16 = idx & 15;
        *(uint4*)&Xp[(size_t)(i0 + r) * 512 + j0 + c16 * 8] = *(const uint4*)&sSt[r * 136 + c16 * 8];
    }
}

// ---------------- kF: LN(X) @ w_z + b_z, * g ---------------------------------
__global__ __launch_bounds__(256) void kF(
    const float* __restrict__ lng, const float* __restrict__ lnb,
    const float* __restrict__ b_z, float* __restrict__ out)
{
    extern __shared__ __half shf[];
    __half* sX = shf;                 // [64][SZS]
    __half* sW = shf + 64 * SZS;      // [128][SZS]
    const int t = threadIdx.x, lane = t & 31, warp = t >> 5;
    const int wy = warp >> 2, lw = warp & 3;
    const int pos0 = blockIdx.x * 64;

    // gather X planes -> transposed smem via stmatrix.trans (conflict-free)
    {
        const int cl = lane >> 2, j = lane & 3;       // channel-in-group, pos pair
        const int srow = 8 * (lane >> 3) + (lane & 7);
        #pragma unroll
        for (int it = 0; it < 4; it++) {
            const int tile = warp * 4 + it;           // 0..31
            const int cg = tile >> 1;                 // channel group (8 ch)
            const int pg = tile & 1;                  // pos group (32 pos)
            const __half* src = d_Xh + (size_t)(cg * 8 + cl) * NPOS + pos0 + pg * 32 + 2 * j;
            const unsigned r0 = *(const unsigned*)(src);
            const unsigned r1 = *(const unsigned*)(src + 8);
            const unsigned r2 = *(const unsigned*)(src + 16);
            const unsigned r3 = *(const unsigned*)(src + 24);
            stsm4t(sX + (pg * 32 + srow) * SZS + cg * 8, r0, r1, r2, r3);
        }
    }
    // load w_z [n][k]
    {
        const uint4* src = (const uint4*)(d_Wt + 5 * 16384);
        #pragma unroll
        for (int l = 0; l < 8; l++) {
            const int idx = t + l * 256;
            const int n = idx >> 4, k8 = (idx & 15) * 8;
            *(uint4*)&sW[n * SZS + k8] = src[idx];
        }
    }
    __syncthreads();
    // LN in place: 8 warps x 8 rows
    {
        const float g0 = lng[lane], g1 = lng[lane + 32], g2 = lng[lane + 64], g3 = lng[lane + 96];
        const float bb0 = lnb[lane], bb1 = lnb[lane + 32], bb2 = lnb[lane + 64], bb3 = lnb[lane + 96];
        #pragma unroll 1
        for (int rr = 0; rr < 8; rr++) {
            const int r = warp * 8 + rr;
            __half* row = sX + r * SZS;
            float v0 = __half2float(row[lane]),      v1 = __half2float(row[lane + 32]);
            float v2 = __half2float(row[lane + 64]), v3 = __half2float(row[lane + 96]);
            float sm = (v0 + v1) + (v2 + v3);
            float sq = fmaf(v0, v0, fmaf(v1, v1, fmaf(v2, v2, v3 * v3)));
            #pragma unroll
            for (int o = 16; o > 0; o >>= 1) {
                sm += __shfl_xor_sync(0xffffffffu, sm, o);
                sq += __shfl_xor_sync(0xffffffffu, sq, o);
            }
            const float mean = sm * 0.0078125f;
            const float var  = fmaf(-mean, mean, sq * 0.0078125f);
            const float rs   = rsqrtf(var + 1e-5f);
            row[lane]      = __float2half_rn(fmaf((v0 - mean) * rs, g0, bb0));
            row[lane + 32] = __float2half_rn(fmaf((v1 - mean) * rs, g1, bb1));
            row[lane + 64] = __float2half_rn(fmaf((v2 - mean) * rs, g2, bb2));
            row[lane + 96] = __float2half_rn(fmaf((v3 - mean) * rs, g3, bb3));
        }
    }
    __syncthreads();

    const int aRow = (lane & 7) + ((lane >> 3) & 1) * 8;
    const int aCol = (lane >> 4) * 8;
    const int bRow = (lane & 7) + ((lane >> 4) & 1) * 8;
    const int bCol = ((lane >> 3) & 1) * 8;

    float acc[2][4][4] = {};
    #pragma unroll
    for (int k0 = 0; k0 < 128; k0 += 16) {
        unsigned af[2][4], bf[2][4];
        #pragma unroll
        for (int mt = 0; mt < 2; mt++)
            ldsm4(af[mt], sX + (wy * 32 + mt * 16 + aRow) * SZS + k0 + aCol);
        #pragma unroll
        for (int p = 0; p < 2; p++)
            ldsm4(bf[p], sW + (lw * 32 + p * 16 + bRow) * SZS + k0 + bCol);
        #pragma unroll
        for (int mt = 0; mt < 2; mt++)
            #pragma unroll
            for (int nt = 0; nt < 4; nt++)
                mma16(acc[mt][nt], af[mt], &bf[nt >> 1][(nt & 1) * 2]);
    }

    #pragma unroll
    for (int mt = 0; mt < 2; mt++)
        #pragma unroll
        for (int nt = 0; nt < 4; nt++) {
            const int r = wy * 32 + mt * 16 + (lane >> 2);
            const int c0 = lw * 32 + nt * 8 + (lane & 3) * 2;
            const float bz0 = b_z[c0], bz1 = b_z[c0 + 1];
            const size_t p0 = (size_t)(pos0 + r) * 128 + c0;
            const size_t p1 = (size_t)(pos0 + r + 8) * 128 + c0;
            const float2 g0 = __half22float2(*(const __half2*)&d_Gh[p0]);
            const float2 g1 = __half22float2(*(const __half2*)&d_Gh[p1]);
            *(float2*)&out[p0] = make_float2((acc[mt][nt][0] + bz0) * g0.x,
                                             (acc[mt][nt][1] + bz1) * g0.y);
            *(float2*)&out[p1] = make_float2((acc[mt][nt][2] + bz0) * g1.x,
                                             (acc[mt][nt][3] + bz1) * g1.y);
        }
}

extern "C" void kernel_launch(void* const* d_in, const int* in_sizes, int n_in,
                              void* d_out, int out_size)
{
    const float* z        = (const float*)d_in[0];
    const float* mask     = (const float*)d_in[1];
    const float* w_ag     = (const float*)d_in[2];
    const float* b_ag     = (const float*)d_in[3];
    const float* w_ap     = (const float*)d_in[4];
    const float* b_ap     = (const float*)d_in[5];
    const float* w_bg     = (const float*)d_in[6];
    const float* b_bg     = (const float*)d_in[7];
    const float* w_bp     = (const float*)d_in[8];
    const float* b_bp     = (const float*)d_in[9];
    const float* w_g      = (const float*)d_in[10];
    const float* b_g      = (const float*)d_in[11];
    const float* w_z      = (const float*)d_in[12];
    const float* b_z      = (const float*)d_in[13];
    const float* ln_in_g  = (const float*)d_in[14];
    const float* ln_in_b  = (const float*)d_in[15];
    const float* ln_out_g = (const float*)d_in[16];
    const float* ln_out_b = (const float*)d_in[17];

    const int KP_SMEM = 4 * 128 * SZS * 2;            // 139264
    const int KE_SMEM = 4 * KEB * 2;                  // 73728
    const int KF_SMEM = (64 + 128) * SZS * 2;         // 52224
    cudaFuncSetAttribute(kP, cudaFuncAttributeMaxDynamicSharedMemorySize, KP_SMEM);
    cudaFuncSetAttribute(kE, cudaFuncAttributeMaxDynamicSharedMemorySize, KE_SMEM);
    cudaFuncSetAttribute(kF, cudaFuncAttributeMaxDynamicSharedMemorySize, KF_SMEM);

    kW<<<6, 256>>>(w_ag, w_ap, w_bg, w_bp, w_g, w_z);
    kP<<<2048, 512, KP_SMEM>>>(z, mask, b_ag, b_ap, b_bg, b_bp, b_g, ln_in_g, ln_in_b);
    kE<<<dim3(4, 4, 128), 256, KE_SMEM>>>();
    kF<<<4096, 256, KF_SMEM>>>(ln_out_g, ln_out_b, b_z, (float*)d_out);
}

// round 7
// speedup vs baseline: 4.7476x; 1.0122x over previous
#include <cuda_runtime.h>
#include <cuda_fp16.h>
#include <cstdint>

// TriangleMultiplicativeUpdate (outgoing), B=1, N=512, C=128. fp16 mma m16n8k16.
// kW: weights -> [n][k] half.
// kP: LN + 5 projections, 64-row blocks, 2 CTAs/SM -> half planes + half G.
// kE: 128 per-channel GEMMs, 128x256 tiles, cp.async double-buffered.
// kF: stmatrix-trans gather of X, LN, @w_z + b_z, * g -> fp32 out.

#define NPOS 262144
#define SZS  136          // smem row stride in halfs (kP/kF)
#define KES  72           // smem row stride in halfs (kE)

__device__ __half d_Wt[6 * 16384];           // [w][n][k]
__device__ __half d_Ah[(size_t)128 * NPOS];  // 64 MB  [c][i*512+k]
__device__ __half d_Bh[(size_t)128 * NPOS];  // 64 MB
__device__ __half d_Xh[(size_t)128 * NPOS];  // 64 MB  [c][i*512+j]
__device__ __half d_Gh[(size_t)NPOS * 128];  // 64 MB  [pos][c]

__device__ __forceinline__ float sigf(float x) { return 1.0f / (1.0f + __expf(-x)); }

__device__ __forceinline__ void mma16(float* d, const unsigned* a, const unsigned* b) {
    asm volatile(
        "mma.sync.aligned.m16n8k16.row.col.f32.f16.f16.f32 "
        "{%0,%1,%2,%3}, {%4,%5,%6,%7}, {%8,%9}, {%0,%1,%2,%3};\n"
        : "+f"(d[0]), "+f"(d[1]), "+f"(d[2]), "+f"(d[3])
        : "r"(a[0]), "r"(a[1]), "r"(a[2]), "r"(a[3]), "r"(b[0]), "r"(b[1]));
}

__device__ __forceinline__ void ldsm4(unsigned* r, const __half* p) {
    unsigned addr = (unsigned)__cvta_generic_to_shared(p);
    asm volatile("ldmatrix.sync.aligned.m8n8.x4.shared.b16 {%0,%1,%2,%3}, [%4];"
                 : "=r"(r[0]), "=r"(r[1]), "=r"(r[2]), "=r"(r[3]) : "r"(addr));
}

__device__ __forceinline__ void stsm4t(__half* p, unsigned r0, unsigned r1,
                                       unsigned r2, unsigned r3) {
    unsigned addr = (unsigned)__cvta_generic_to_shared(p);
    asm volatile("stmatrix.sync.aligned.m8n8.x4.trans.shared.b16 [%0], {%1,%2,%3,%4};"
                 :: "r"(addr), "r"(r0), "r"(r1), "r"(r2), "r"(r3) : "memory");
}

__device__ __forceinline__ void cp16(void* s, const void* g) {
    unsigned sa = (unsigned)__cvta_generic_to_shared(s);
    asm volatile("cp.async.cg.shared.global [%0], [%1], 16;" :: "r"(sa), "l"(g));
}
#define CPCOMMIT() asm volatile("cp.async.commit_group;")
#define CPWAIT(n)  asm volatile("cp.async.wait_group %0;" :: "n"(n))

// ---------------- kW: weight transpose+convert ------------------------------
__global__ __launch_bounds__(256) void kW(
    const float* __restrict__ w_ag, const float* __restrict__ w_ap,
    const float* __restrict__ w_bg, const float* __restrict__ w_bp,
    const float* __restrict__ w_g,  const float* __restrict__ w_z)
{
    __shared__ float s[128 * 132];
    const float* srcs[6] = {w_ag, w_ap, w_bg, w_bp, w_g, w_z};
    const float* w = srcs[blockIdx.x];
    const int t = threadIdx.x;
    #pragma unroll
    for (int l = 0; l < 64; l++) {
        const int idx = t + l * 256;
        s[(idx >> 7) * 132 + (idx & 127)] = w[idx];   // [k][n]
    }
    __syncthreads();
    __half* dst = d_Wt + blockIdx.x * 16384;
    #pragma unroll
    for (int l = 0; l < 64; l++) {
        const int idx = t + l * 256;                  // idx = n*128 + k
        dst[idx] = __float2half_rn(s[(idx & 127) * 132 + (idx >> 7)]);
    }
}

// ---------------- kP: 64-row blocks, 256 threads, 2 CTAs/SM ------------------
__device__ __forceinline__ void prefW(__half* buf, const __half* __restrict__ wt, int t) {
    #pragma unroll
    for (int l = 0; l < 8; l++) {
        const int idx = t + l * 256;                 // 2048 uint4
        const int n = idx >> 4, k8 = (idx & 15) * 8;
        cp16(&buf[n * SZS + k8], &wt[n * 128 + k8]);
    }
    CPCOMMIT();
}

// 64x128 GEMM: 8 warps in 2(M) x 4(N), warp tile 32x32.
__device__ __forceinline__ void gemmC(
    const __half* sW, const __half* sZ, float acc[2][4][4],
    int wy, int lw, int aRow, int aCol, int bRow, int bCol)
{
    #pragma unroll
    for (int k0 = 0; k0 < 128; k0 += 16) {
        unsigned af[2][4], bf[2][4];
        #pragma unroll
        for (int mt = 0; mt < 2; mt++)
            ldsm4(af[mt], sZ + (wy * 32 + mt * 16 + aRow) * SZS + k0 + aCol);
        #pragma unroll
        for (int p = 0; p < 2; p++)
            ldsm4(bf[p], sW + (lw * 32 + p * 16 + bRow) * SZS + k0 + bCol);
        #pragma unroll
        for (int mt = 0; mt < 2; mt++)
            #pragma unroll
            for (int nt = 0; nt < 4; nt++)
                mma16(acc[mt][nt], af[mt], &bf[nt >> 1][(nt & 1) * 2]);
    }
}

__global__ __launch_bounds__(256, 2) void kP(
    const float* __restrict__ z,    const float* __restrict__ mask,
    const float* __restrict__ b_ag, const float* __restrict__ b_ap,
    const float* __restrict__ b_bg, const float* __restrict__ b_bp,
    const float* __restrict__ b_g,
    const float* __restrict__ lng,  const float* __restrict__ lnb)
{
    extern __shared__ __half sh[];
    __half* sZ  = sh;                             // [64][SZS]
    __half* sW0 = sh + 64 * SZS;                  // [128][SZS]
    __half* sW1 = sh + 64 * SZS + 128 * SZS;      // [128][SZS]
    __half* sSt = sh + 64 * SZS + 2 * 128 * SZS;  // [64][SZS]
    const int t = threadIdx.x, lane = t & 31, warp = t >> 5;
    const int wy = warp >> 2, lw = warp & 3;
    const int pos0 = blockIdx.x * 64;

    prefW(sW0, d_Wt + 0 * 16384, t);   // w_ag in flight during LN

    {
        const float g0 = lng[lane], g1 = lng[lane + 32], g2 = lng[lane + 64], g3 = lng[lane + 96];
        const float bb0 = lnb[lane], bb1 = lnb[lane + 32], bb2 = lnb[lane + 64], bb3 = lnb[lane + 96];
        #pragma unroll 1
        for (int rr = 0; rr < 8; rr++) {
            const int r = warp * 8 + rr;
            const float* zr = z + (size_t)(pos0 + r) * 128;
            float v0 = zr[lane], v1 = zr[lane + 32], v2 = zr[lane + 64], v3 = zr[lane + 96];
            float sm = (v0 + v1) + (v2 + v3);
            float sq = fmaf(v0, v0, fmaf(v1, v1, fmaf(v2, v2, v3 * v3)));
            #pragma unroll
            for (int o = 16; o > 0; o >>= 1) {
                sm += __shfl_xor_sync(0xffffffffu, sm, o);
                sq += __shfl_xor_sync(0xffffffffu, sq, o);
            }
            const float mean = sm * 0.0078125f;
            const float var  = fmaf(-mean, mean, sq * 0.0078125f);
            const float rs   = rsqrtf(var + 1e-5f);
            sZ[r * SZS + lane]      = __float2half_rn(fmaf((v0 - mean) * rs, g0, bb0));
            sZ[r * SZS + lane + 32] = __float2half_rn(fmaf((v1 - mean) * rs, g1, bb1));
            sZ[r * SZS + lane + 64] = __float2half_rn(fmaf((v2 - mean) * rs, g2, bb2));
            sZ[r * SZS + lane + 96] = __float2half_rn(fmaf((v3 - mean) * rs, g3, bb3));
        }
    }
    prefW(sW1, d_Wt + 1 * 16384, t);   // w_ap

    const int aRow = (lane & 7) + ((lane >> 3) & 1) * 8;
    const int aCol = (lane >> 4) * 8;
    const int bRow = (lane & 7) + ((lane >> 4) & 1) * 8;
    const int bCol = ((lane >> 3) & 1) * 8;
    const int rB = wy * 32 + (lane >> 2);
    const int cB = lw * 32 + (lane & 3) * 2;

    #pragma unroll 1
    for (int pair = 0; pair < 2; pair++) {
        const float* biasG = pair ? b_bg : b_ag;
        const float* biasP = pair ? b_bp : b_ap;
        __half* plane = pair ? d_Bh : d_Ah;

        float accg[2][4][4] = {};
        CPWAIT(1);
        __syncthreads();
        gemmC(sW0, sZ, accg, wy, lw, aRow, aCol, bRow, bCol);
        __syncthreads();
        if (pair == 0) prefW(sW0, d_Wt + 2 * 16384, t);   // w_bg
        else           prefW(sW0, d_Wt + 4 * 16384, t);   // w_g
        #pragma unroll
        for (int mt = 0; mt < 2; mt++)
            #pragma unroll
            for (int nt = 0; nt < 4; nt++) {
                const int c = cB + nt * 8;
                const float bg0 = biasG[c], bg1 = biasG[c + 1];
                accg[mt][nt][0] = sigf(accg[mt][nt][0] + bg0);
                accg[mt][nt][1] = sigf(accg[mt][nt][1] + bg1);
                accg[mt][nt][2] = sigf(accg[mt][nt][2] + bg0);
                accg[mt][nt][3] = sigf(accg[mt][nt][3] + bg1);
            }

        float accp[2][4][4] = {};
        CPWAIT(1);
        __syncthreads();
        gemmC(sW1, sZ, accp, wy, lw, aRow, aCol, bRow, bCol);
        __syncthreads();
        if (pair == 0) prefW(sW1, d_Wt + 3 * 16384, t);   // w_bp

        #pragma unroll
        for (int mt = 0; mt < 2; mt++) {
            const int r = rB + mt * 16;
            const float m0 = mask[pos0 + r], m1 = mask[pos0 + r + 8];
            #pragma unroll
            for (int nt = 0; nt < 4; nt++) {
                const int c = cB + nt * 8;
                const float bp0 = biasP[c], bp1 = biasP[c + 1];
                *(__half2*)&sSt[r * SZS + c] = __floats2half2_rn(
                    m0 * accg[mt][nt][0] * (accp[mt][nt][0] + bp0),
                    m0 * accg[mt][nt][1] * (accp[mt][nt][1] + bp1));
                *(__half2*)&sSt[(r + 8) * SZS + c] = __floats2half2_rn(
                    m1 * accg[mt][nt][2] * (accp[mt][nt][2] + bp0),
                    m1 * accg[mt][nt][3] * (accp[mt][nt][3] + bp1));
            }
        }
        __syncthreads();
        // transposed flush: [p][c] -> plane[c][pos0+p]
        #pragma unroll
        for (int l = 0; l < 32; l++) {
            const int idx = t + l * 256;       // 0..8191
            const int c = idx >> 6, p = idx & 63;
            plane[(size_t)c * NPOS + pos0 + p] = sSt[p * SZS + c];
        }
    }

    // g pass
    {
        float accq[2][4][4] = {};
        CPWAIT(0);
        __syncthreads();
        gemmC(sW0, sZ, accq, wy, lw, aRow, aCol, bRow, bCol);
        #pragma unroll
        for (int mt = 0; mt < 2; mt++) {
            const int r = rB + mt * 16;
            #pragma unroll
            for (int nt = 0; nt < 4; nt++) {
                const int c = cB + nt * 8;
                const float bg0 = b_g[c], bg1 = b_g[c + 1];
                *(__half2*)&d_Gh[(size_t)(pos0 + r) * 128 + c] =
                    __floats2half2_rn(sigf(accq[mt][nt][0] + bg0), sigf(accq[mt][nt][1] + bg1));
                *(__half2*)&d_Gh[(size_t)(pos0 + r + 8) * 128 + c] =
                    __floats2half2_rn(sigf(accq[mt][nt][2] + bg0), sigf(accq[mt][nt][3] + bg1));
            }
        }
    }
}

// ---------------- kE: per-channel GEMM, 128x256 tile, cp.async --------------
// 256 threads, 8 warps in 2(M) x 4(N), warp tile 64x64. K=512 in 8 chunks of 64.
#define KE_STAGEH 27648                       // halfs per stage: A 128*72 + B 256*72
#define KE_SMEM   (2 * KE_STAGEH * 2)         // 110592 bytes

__global__ __launch_bounds__(256) void kE()
{
    extern __shared__ __half she[];
    const int t = threadIdx.x, lane = t & 31, warp = t >> 5;
    const int wy = warp >> 2, lw = warp & 3;
    const int j0 = blockIdx.x * 256, i0 = blockIdx.y * 128, ch = blockIdx.z;
    const __half* __restrict__ Ap = d_Ah + (size_t)ch * NPOS;
    const __half* __restrict__ Bp = d_Bh + (size_t)ch * NPOS;

    const int aRow = (lane & 7) + ((lane >> 3) & 1) * 8;
    const int aCol = (lane >> 4) * 8;
    const int bRow = (lane & 7) + ((lane >> 4) & 1) * 8;
    const int bCol = ((lane >> 3) & 1) * 8;

    const int lr = t >> 3, lk8 = (t & 7) * 8;    // 32 rows x 8 chunks per pass

    auto load_chunk = [&](int c, int stage) {
        __half* sA = she + stage * KE_STAGEH;
        __half* sB = sA + 128 * KES;
        const int kt = c * 64;
        #pragma unroll
        for (int l = 0; l < 4; l++) {            // A: 128 rows
            const int r = lr + l * 32;
            cp16(&sA[r * KES + lk8], &Ap[(size_t)(i0 + r) * 512 + kt + lk8]);
        }
        #pragma unroll
        for (int l = 0; l < 8; l++) {            // B: 256 rows
            const int r = lr + l * 32;
            cp16(&sB[r * KES + lk8], &Bp[(size_t)(j0 + r) * 512 + kt + lk8]);
        }
        CPCOMMIT();
    };

    float acc[4][8][4] = {};

    load_chunk(0, 0);

    #pragma unroll 1
    for (int s = 0; s < 8; s++) {
        if (s < 7) {
            load_chunk(s + 1, (s + 1) & 1);
            CPWAIT(1);
        } else {
            CPWAIT(0);
        }
        __syncthreads();
        const __half* bA = she + (s & 1) * KE_STAGEH;
        const __half* bB = bA + 128 * KES;
        #pragma unroll
        for (int kk = 0; kk < 64; kk += 16) {
            unsigned af[4][4], bf[4][4];
            #pragma unroll
            for (int mt = 0; mt < 4; mt++)
                ldsm4(af[mt], bA + (wy * 64 + mt * 16 + aRow) * KES + kk + aCol);
            #pragma unroll
            for (int p = 0; p < 4; p++)
                ldsm4(bf[p], bB + (lw * 64 + p * 16 + bRow) * KES + kk + bCol);
            #pragma unroll
            for (int mt = 0; mt < 4; mt++)
                #pragma unroll
                for (int nt = 0; nt < 8; nt++)
                    mma16(acc[mt][nt], af[mt], &bf[nt >> 1][(nt & 1) * 2]);
        }
        __syncthreads();
    }

    // stage output through smem: 128 rows x 264 halfs (67.6 KB, fits in 108 KB)
    __half* sSt = she;
    #pragma unroll
    for (int mt = 0; mt < 4; mt++)
        #pragma unroll
        for (int nt = 0; nt < 8; nt++) {
            const int r = wy * 64 + mt * 16 + (lane >> 2);
            const int c = lw * 64 + nt * 8 + (lane & 3) * 2;
            *(__half2*)&sSt[r * 264 + c]       = __floats2half2_rn(acc[mt][nt][0], acc[mt][nt][1]);
            *(__half2*)&sSt[(r + 8) * 264 + c] = __floats2half2_rn(acc[mt][nt][2], acc[mt][nt][3]);
        }
    __syncthreads();
    __half* Xp = d_Xh + (size_t)ch * NPOS;
    #pragma unroll
    for (int l = 0; l < 16; l++) {
        const int idx = t + l * 256;             // 4096 16B chunks
        const int r = idx >> 5, c16 = idx & 31;
        *(uint4*)&Xp[(size_t)(i0 + r) * 512 + j0 + c16 * 8] = *(const uint4*)&sSt[r * 264 + c16 * 8];
    }
}

// ---------------- kF: LN(X) @ w_z + b_z, * g ---------------------------------
__global__ __launch_bounds__(256) void kF(
    const float* __restrict__ lng, const float* __restrict__ lnb,
    const float* __restrict__ b_z, float* __restrict__ out)
{
    extern __shared__ __half shf[];
    __half* sX = shf;                 // [64][SZS]
    __half* sW = shf + 64 * SZS;      // [128][SZS]
    const int t = threadIdx.x, lane = t & 31, warp = t >> 5;
    const int wy = warp >> 2, lw = warp & 3;
    const int pos0 = blockIdx.x * 64;

    {
        const int cl = lane >> 2, j = lane & 3;
        const int srow = 8 * (lane >> 3) + (lane & 7);
        #pragma unroll
        for (int it = 0; it < 4; it++) {
            const int tile = warp * 4 + it;
            const int cg = tile >> 1;
            const int pg = tile & 1;
            const __half* src = d_Xh + (size_t)(cg * 8 + cl) * NPOS + pos0 + pg * 32 + 2 * j;
            const unsigned r0 = *(const unsigned*)(src);
            const unsigned r1 = *(const unsigned*)(src + 8);
            const unsigned r2 = *(const unsigned*)(src + 16);
            const unsigned r3 = *(const unsigned*)(src + 24);
            stsm4t(sX + (pg * 32 + srow) * SZS + cg * 8, r0, r1, r2, r3);
        }
    }
    {
        const uint4* src = (const uint4*)(d_Wt + 5 * 16384);
        #pragma unroll
        for (int l = 0; l < 8; l++) {
            const int idx = t + l * 256;
            const int n = idx >> 4, k8 = (idx & 15) * 8;
            *(uint4*)&sW[n * SZS + k8] = src[idx];
        }
    }
    __syncthreads();
    {
        const float g0 = lng[lane], g1 = lng[lane + 32], g2 = lng[lane + 64], g3 = lng[lane + 96];
        const float bb0 = lnb[lane], bb1 = lnb[lane + 32], bb2 = lnb[lane + 64], bb3 = lnb[lane + 96];
        #pragma unroll 1
        for (int rr = 0; rr < 8; rr++) {
            const int r = warp * 8 + rr;
            __half* row = sX + r * SZS;
            float v0 = __half2float(row[lane]),      v1 = __half2float(row[lane + 32]);
            float v2 = __half2float(row[lane + 64]), v3 = __half2float(row[lane + 96]);
            float sm = (v0 + v1) + (v2 + v3);
            float sq = fmaf(v0, v0, fmaf(v1, v1, fmaf(v2, v2, v3 * v3)));
            #pragma unroll
            for (int o = 16; o > 0; o >>= 1) {
                sm += __shfl_xor_sync(0xffffffffu, sm, o);
                sq += __shfl_xor_sync(0xffffffffu, sq, o);
            }
            const float mean = sm * 0.0078125f;
            const float var  = fmaf(-mean, mean, sq * 0.0078125f);
            const float rs   = rsqrtf(var + 1e-5f);
            row[lane]      = __float2half_rn(fmaf((v0 - mean) * rs, g0, bb0));
            row[lane + 32] = __float2half_rn(fmaf((v1 - mean) * rs, g1, bb1));
            row[lane + 64] = __float2half_rn(fmaf((v2 - mean) * rs, g2, bb2));
            row[lane + 96] = __float2half_rn(fmaf((v3 - mean) * rs, g3, bb3));
        }
    }
    __syncthreads();

    const int aRow = (lane & 7) + ((lane >> 3) & 1) * 8;
    const int aCol = (lane >> 4) * 8;
    const int bRow = (lane & 7) + ((lane >> 4) & 1) * 8;
    const int bCol = ((lane >> 3) & 1) * 8;

    float acc[2][4][4] = {};
    #pragma unroll
    for (int k0 = 0; k0 < 128; k0 += 16) {
        unsigned af[2][4], bf[2][4];
        #pragma unroll
        for (int mt = 0; mt < 2; mt++)
            ldsm4(af[mt], sX + (wy * 32 + mt * 16 + aRow) * SZS + k0 + aCol);
        #pragma unroll
        for (int p = 0; p < 2; p++)
            ldsm4(bf[p], sW + (lw * 32 + p * 16 + bRow) * SZS + k0 + bCol);
        #pragma unroll
        for (int mt = 0; mt < 2; mt++)
            #pragma unroll
            for (int nt = 0; nt < 4; nt++)
                mma16(acc[mt][nt], af[mt], &bf[nt >> 1][(nt & 1) * 2]);
    }

    #pragma unroll
    for (int mt = 0; mt < 2; mt++)
        #pragma unroll
        for (int nt = 0; nt < 4; nt++) {
            const int r = wy * 32 + mt * 16 + (lane >> 2);
            const int c0 = lw * 32 + nt * 8 + (lane & 3) * 2;
            const float bz0 = b_z[c0], bz1 = b_z[c0 + 1];
            const size_t p0 = (size_t)(pos0 + r) * 128 + c0;
            const size_t p1 = (size_t)(pos0 + r + 8) * 128 + c0;
            const float2 g0 = __half22float2(*(const __half2*)&d_Gh[p0]);
            const float2 g1 = __half22float2(*(const __half2*)&d_Gh[p1]);
            *(float2*)&out[p0] = make_float2((acc[mt][nt][0] + bz0) * g0.x,
                                             (acc[mt][nt][1] + bz1) * g0.y);
            *(float2*)&out[p1] = make_float2((acc[mt][nt][2] + bz0) * g1.x,
                                             (acc[mt][nt][3] + bz1) * g1.y);
        }
}

extern "C" void kernel_launch(void* const* d_in, const int* in_sizes, int n_in,
                              void* d_out, int out_size)
{
    const float* z        = (const float*)d_in[0];
    const float* mask     = (const float*)d_in[1];
    const float* w_ag     = (const float*)d_in[2];
    const float* b_ag     = (const float*)d_in[3];
    const float* w_ap     = (const float*)d_in[4];
    const float* b_ap     = (const float*)d_in[5];
    const float* w_bg     = (const float*)d_in[6];
    const float* b_bg     = (const float*)d_in[7];
    const float* w_bp     = (const float*)d_in[8];
    const float* b_bp     = (const float*)d_in[9];
    const float* w_g      = (const float*)d_in[10];
    const float* b_g      = (const float*)d_in[11];
    const float* w_z      = (const float*)d_in[12];
    const float* b_z      = (const float*)d_in[13];
    const float* ln_in_g  = (const float*)d_in[14];
    const float* ln_in_b  = (const float*)d_in[15];
    const float* ln_out_g = (const float*)d_in[16];
    const float* ln_out_b = (const float*)d_in[17];

    const int KP_SMEM = (64 + 2 * 128 + 64) * SZS * 2;   // 104448
    const int KF_SMEM = (64 + 128) * SZS * 2;            // 52224
    cudaFuncSetAttribute(kP, cudaFuncAttributeMaxDynamicSharedMemorySize, KP_SMEM);
    cudaFuncSetAttribute(kE, cudaFuncAttributeMaxDynamicSharedMemorySize, KE_SMEM);
    cudaFuncSetAttribute(kF, cudaFuncAttributeMaxDynamicSharedMemorySize, KF_SMEM);

    kW<<<6, 256>>>(w_ag, w_ap, w_bg, w_bp, w_g, w_z);
    kP<<<4096, 256, KP_SMEM>>>(z, mask, b_ag, b_ap, b_bg, b_bp, b_g, ln_in_g, ln_in_b);
    kE<<<dim3(2, 4, 128), 256, KE_SMEM>>>();
    kF<<<4096, 256, KF_SMEM>>>(ln_out_g, ln_out_b, b_z, (float*)d_out);
}